// round 4
// baseline (speedup 1.0000x reference)
#include <cuda_runtime.h>
#include <cstdint>

#define BATCH 16
#define CIN   512
#define COUT  512
#define NPIX  4096
#define MOD_SCALE  0.044194173824159216f
#define CONV_SCALE 0.014731391274719739f

#define XH    13056   // 32 ci * 408 (6 rows * 68 cols, padded stride)
#define XSTR  408
#define WTILE 4096    // 128 o * 32 ci packed frags
#define CONV_SMEM (2*XH*4 + 2*WTILE*4)   // 137216 bytes

// ---------------- device scratch ----------------
__device__ float g_s[BATCH*CIN];
__device__ float g_wsq[COUT*CIN];
__device__ float g_dscale[BATCH*COUT];
__device__ float g_wpack[9*COUT*CIN];          // 9.4 MB, frag-packed tf32
__device__ float g_xs[BATCH*CIN*NPIX];         // 134 MB, s-scaled tf32 input

__device__ __forceinline__ float tf32_rna(float x){
    uint32_t u;
    asm("cvt.rna.tf32.f32 %0, %1;" : "=r"(u) : "f"(x));
    return __uint_as_float(u);
}

// ---------------- s[b][ci] = style @ (mod_weight*MOD_SCALE)^T + bias ----------------
__global__ void mod_kernel(const float* __restrict__ style,
                           const float* __restrict__ mod_weight,
                           const float* __restrict__ mod_bias){
    __shared__ float st[512];
    int b = blockIdx.x, t = threadIdx.x;
    st[t] = style[b*512 + t];
    __syncthreads();
    const float* wr = mod_weight + t*512;
    float acc = 0.f;
    #pragma unroll 8
    for (int j = 0; j < 512; j++) acc = fmaf(st[j], wr[j], acc);
    g_s[b*512 + t] = acc * MOD_SCALE + mod_bias[t];
}

// ---------------- wsq[o][ci] = sum_t weight^2 ----------------
__global__ void wsq_kernel(const float* __restrict__ w){
    int i = blockIdx.x*blockDim.x + threadIdx.x;   // 262144
    const float* p = w + i*9;
    float a = 0.f;
    #pragma unroll
    for (int t = 0; t < 9; t++) a = fmaf(p[t], p[t], a);
    g_wsq[i] = a;
}

// ---------------- dscale[b][o] = CONV_SCALE * rsqrt(CONV_SCALE^2 * sum s^2*wsq + 1e-8) ----------------
__global__ void demod_kernel(){
    __shared__ float s2[512];
    int b = blockIdx.x, t = threadIdx.x;
    float sv = g_s[b*512 + t];
    s2[t] = sv*sv;
    __syncthreads();
    const float* wr = g_wsq + t*512;
    float acc = 0.f;
    #pragma unroll 8
    for (int j = 0; j < 512; j++) acc = fmaf(s2[j], wr[j], acc);
    float v = CONV_SCALE*CONV_SCALE*acc + 1e-8f;
    g_dscale[b*512 + t] = CONV_SCALE / sqrtf(v);
}

// ---------------- pack W into mma-fragment layout, tf32-rounded ----------------
// layout: [tap][cic(16)][ob(4)][ks(4)][mt(8)][lane(32)][reg(4)]
__global__ void pack_kernel(const float* __restrict__ w){
    int i = blockIdx.x*256 + threadIdx.x;          // 2359296 = 512*512*9, coalesced read
    int o   = i / 4608;
    int rem = i - o*4608;
    int ci  = rem / 9;
    int tap = rem - ci*9;
    int cic = ci >> 5, ks = (ci >> 3) & 3;
    int ob  = o  >> 7, mt = (o  >> 4) & 7;
    int lane = ((o & 7) << 2) | (ci & 3);
    int reg  = ((o >> 3) & 1) | (((ci >> 2) & 1) << 1);
    int q = (((tap*16 + cic)*4 + ob) << 12) + ((((ks*8 + mt) << 5) + lane) << 2) + reg;
    g_wpack[q] = tf32_rna(w[i]);
}

// ---------------- xs = tf32_rna(s[b,ci] * x) ----------------
__global__ void xscale_kernel(const float4* __restrict__ x){
    int i = blockIdx.x*blockDim.x + threadIdx.x;   // 8388608 float4
    int bc = i >> 10;                              // 1024 float4 per (b,ci) plane
    float s = g_s[bc];
    float4 v = x[i];
    v.x = tf32_rna(v.x * s);
    v.y = tf32_rna(v.y * s);
    v.z = tf32_rna(v.z * s);
    v.w = tf32_rna(v.w * s);
    ((float4*)g_xs)[i] = v;
}

// ---------------- main implicit conv (per-batch GEMM, 9 taps per ci-chunk) ----------------
__device__ __forceinline__ void mma_tf32(float* c, uint32_t a0,uint32_t a1,uint32_t a2,uint32_t a3,
                                         uint32_t b0,uint32_t b1){
    asm volatile("mma.sync.aligned.m16n8k8.row.col.f32.tf32.tf32.f32 "
        "{%0,%1,%2,%3}, {%4,%5,%6,%7}, {%8,%9}, {%0,%1,%2,%3};"
        : "+f"(c[0]), "+f"(c[1]), "+f"(c[2]), "+f"(c[3])
        : "r"(a0), "r"(a1), "r"(a2), "r"(a3), "r"(b0), "r"(b1));
}

__global__ __launch_bounds__(256,1) void conv_kernel(float* __restrict__ out){
    extern __shared__ float smem[];
    float* sX = smem;                 // [2][13056]  halo tiles
    float* sW = smem + 2*XH;          // [2][4096]   packed W frags

    const int tid  = threadIdx.x;
    const int lane = tid & 31;
    const int warp = tid >> 5;
    const int wm   = warp >> 2;       // 0..1  (64 out-ch each)
    const int wn   = warp & 3;        // 0..3  (one image row each)
    const int ob = blockIdx.x;        // out-ch block (128)
    const int rt = blockIdx.y;        // row tile (4 rows)
    const int b  = blockIdx.z;        // batch
    const int r0 = rt * 4;

    unsigned sx_u = (unsigned)__cvta_generic_to_shared(sX);
    unsigned sw_u = (unsigned)__cvta_generic_to_shared(sW);

    const float* xg = g_xs + (size_t)b * (CIN*NPIX);

    float acc[4][8][4];
    #pragma unroll
    for (int i=0;i<4;i++)
      #pragma unroll
      for (int j=0;j<8;j++)
        #pragma unroll
        for (int k=0;k<4;k++) acc[i][j][k]=0.f;

    auto load_x = [&](int chunk){
        unsigned sb = sx_u + (unsigned)((chunk & 1) * XH) * 4u;
        const float* gx = xg + chunk * 32 * NPIX;
        for (int i = tid; i < XH; i += 256){
            int ci  = i / XSTR;
            int rem = i - ci * XSTR;
            int r = rem / 68;
            int c = rem - r * 68;
            int grow = r0 - 1 + r;
            int gcol = c - 1;
            bool ok = ((unsigned)grow < 64u) && ((unsigned)gcol < 64u);
            const float* ga = gx + ci * NPIX + (ok ? (grow * 64 + gcol) : 0);
            int sz = ok ? 4 : 0;
            asm volatile("cp.async.ca.shared.global [%0], [%1], 4, %2;"
                         :: "r"(sb + (unsigned)i * 4u), "l"(ga), "r"(sz));
        }
    };

    auto load_w = [&](int step){
        int chunk = step / 9;
        int tap   = step - chunk * 9;
        const float* gw = g_wpack + (((tap*16 + chunk)*4 + ob) << 12);
        unsigned sb = sw_u + (unsigned)((step & 1) * WTILE) * 4u;
        #pragma unroll
        for (int i = 0; i < 4; i++){
            int idx = tid + i * 256;
            asm volatile("cp.async.cg.shared.global [%0], [%1], 16;"
                         :: "r"(sb + (unsigned)idx * 16u), "l"(gw + idx * 4));
        }
    };

    load_x(0);
    load_w(0);
    asm volatile("cp.async.commit_group;");
    asm volatile("cp.async.wait_group 0;");
    __syncthreads();

    for (int step = 0; step < 144; step++){        // 16 ci-chunks * 9 taps
        int chunk = step / 9;
        int tap   = step - chunk * 9;
        if (tap == 0 && chunk < 15) load_x(chunk + 1);
        if (step < 143) load_w(step + 1);
        asm volatile("cp.async.commit_group;");

        const int dh = tap / 3;
        const int dw = tap - dh * 3;
        const float* xb = sX + (chunk & 1) * XH + (wn + dh) * 68 + dw + (lane >> 2);
        const float4* w4 = (const float4*)(sW + (step & 1) * WTILE);

        #pragma unroll
        for (int ks = 0; ks < 4; ks++){
            const float* xp = xb + (ks * 8 + (lane & 3)) * XSTR;
            uint32_t bf[8][2];
            #pragma unroll
            for (int nt = 0; nt < 8; nt++){
                bf[nt][0] = __float_as_uint(xp[nt*8]);
                bf[nt][1] = __float_as_uint(xp[nt*8 + 4*XSTR]);
            }
            #pragma unroll
            for (int mt = 0; mt < 4; mt++){
                float4 a = w4[(ks*8 + wm*4 + mt)*32 + lane];
                uint32_t a0=__float_as_uint(a.x), a1=__float_as_uint(a.y),
                         a2=__float_as_uint(a.z), a3=__float_as_uint(a.w);
                #pragma unroll
                for (int nt = 0; nt < 8; nt++)
                    mma_tf32(acc[mt][nt], a0,a1,a2,a3, bf[nt][0], bf[nt][1]);
            }
        }
        asm volatile("cp.async.wait_group 0;");
        __syncthreads();
    }

    // epilogue: scale by dscale[b][o] and store
    const int rowpx = (r0 + wn) * 64;
    #pragma unroll
    for (int mt = 0; mt < 4; mt++){
        int o0 = ob*128 + wm*64 + mt*16 + (lane >> 2);
        float d0 = g_dscale[b*512 + o0];
        float d1 = g_dscale[b*512 + o0 + 8];
        float* p0 = out + (size_t)(b*512 + o0) * NPIX + rowpx + (lane & 3)*2;
        float* p1 = p0 + (size_t)8 * NPIX;
        #pragma unroll
        for (int nt = 0; nt < 8; nt++){
            float2 v0 = make_float2(acc[mt][nt][0]*d0, acc[mt][nt][1]*d0);
            float2 v1 = make_float2(acc[mt][nt][2]*d1, acc[mt][nt][3]*d1);
            *(float2*)(p0 + nt*8) = v0;
            *(float2*)(p1 + nt*8) = v1;
        }
    }
}

// ---------------- launcher ----------------
extern "C" void kernel_launch(void* const* d_in, const int* in_sizes, int n_in,
                              void* d_out, int out_size){
    const float* input      = (const float*)d_in[0];
    const float* style      = (const float*)d_in[1];
    const float* weight     = (const float*)d_in[2];
    const float* mod_weight = (const float*)d_in[3];
    const float* mod_bias   = (const float*)d_in[4];
    float* out = (float*)d_out;

    cudaFuncSetAttribute(conv_kernel, cudaFuncAttributeMaxDynamicSharedMemorySize, CONV_SMEM);

    mod_kernel   <<<16, 512>>>(style, mod_weight, mod_bias);
    wsq_kernel   <<<1024, 256>>>(weight);
    demod_kernel <<<16, 512>>>();
    pack_kernel  <<<9216, 256>>>(weight);
    xscale_kernel<<<8192, 1024>>>((const float4*)input);
    conv_kernel  <<<dim3(4,16,16), 256, CONV_SMEM>>>(out);
}

// round 5
// speedup vs baseline: 1.0011x; 1.0011x over previous
#include <cuda_runtime.h>
#include <cstdint>

#define BATCH 16
#define CIN   512
#define COUT  512
#define NPIX  4096
#define MOD_SCALE  0.044194173824159216f
#define CONV_SCALE 0.014731391274719739f

#define XH    13056   // 32 ci * 408 (6 rows * 68 cols, padded stride)
#define XSTR  408
#define WTILE 4096    // 128 o * 32 ci packed frags
#define CONV_SMEM (2*XH*4 + 2*WTILE*4)   // 137216 bytes

// ---------------- device scratch ----------------
__device__ float g_s[BATCH*CIN];
__device__ float g_wsq[COUT*CIN];
__device__ float g_dscale[BATCH*COUT];
__device__ float g_wpack[9*COUT*CIN];          // 9.4 MB, frag-packed tf32
__device__ float g_xs[BATCH*CIN*NPIX];         // 134 MB, s-scaled tf32 input

__device__ __forceinline__ float tf32_rna(float x){
    uint32_t u;
    asm("cvt.rna.tf32.f32 %0, %1;" : "=r"(u) : "f"(x));
    return __uint_as_float(u);
}

// ---------------- s[b][ci] = style @ (mod_weight*MOD_SCALE)^T + bias ----------------
__global__ void mod_kernel(const float* __restrict__ style,
                           const float* __restrict__ mod_weight,
                           const float* __restrict__ mod_bias){
    __shared__ float st[512];
    int b = blockIdx.x, t = threadIdx.x;
    st[t] = style[b*512 + t];
    __syncthreads();
    const float* wr = mod_weight + t*512;
    float acc = 0.f;
    #pragma unroll 8
    for (int j = 0; j < 512; j++) acc = fmaf(st[j], wr[j], acc);
    g_s[b*512 + t] = acc * MOD_SCALE + mod_bias[t];
}

// ---------------- wsq[o][ci] = sum_t weight^2 ----------------
__global__ void wsq_kernel(const float* __restrict__ w){
    int i = blockIdx.x*blockDim.x + threadIdx.x;   // 262144
    const float* p = w + i*9;
    float a = 0.f;
    #pragma unroll
    for (int t = 0; t < 9; t++) a = fmaf(p[t], p[t], a);
    g_wsq[i] = a;
}

// ---------------- dscale[b][o] = CONV_SCALE * rsqrt(CONV_SCALE^2 * sum s^2*wsq + 1e-8) ----------------
__global__ void demod_kernel(){
    __shared__ float s2[512];
    int b = blockIdx.x, t = threadIdx.x;
    float sv = g_s[b*512 + t];
    s2[t] = sv*sv;
    __syncthreads();
    const float* wr = g_wsq + t*512;
    float acc = 0.f;
    #pragma unroll 8
    for (int j = 0; j < 512; j++) acc = fmaf(s2[j], wr[j], acc);
    float v = CONV_SCALE*CONV_SCALE*acc + 1e-8f;
    g_dscale[b*512 + t] = CONV_SCALE / sqrtf(v);
}

// ---------------- pack W into mma-fragment layout, tf32-rounded ----------------
// layout: [tap][cic(16)][ob(4)][ks(4)][mt(8)][lane(32)][reg(4)]
__global__ void pack_kernel(const float* __restrict__ w){
    int i = blockIdx.x*256 + threadIdx.x;          // 2359296 = 512*512*9, coalesced read
    int o   = i / 4608;
    int rem = i - o*4608;
    int ci  = rem / 9;
    int tap = rem - ci*9;
    int cic = ci >> 5, ks = (ci >> 3) & 3;
    int ob  = o  >> 7, mt = (o  >> 4) & 7;
    int lane = ((o & 7) << 2) | (ci & 3);
    int reg  = ((o >> 3) & 1) | (((ci >> 2) & 1) << 1);
    int q = (((tap*16 + cic)*4 + ob) << 12) + ((((ks*8 + mt) << 5) + lane) << 2) + reg;
    g_wpack[q] = tf32_rna(w[i]);
}

// ---------------- xs = tf32_rna(s[b,ci] * x) ----------------
__global__ void xscale_kernel(const float4* __restrict__ x){
    int i = blockIdx.x*blockDim.x + threadIdx.x;   // 8388608 float4
    int bc = i >> 10;                              // 1024 float4 per (b,ci) plane
    float s = g_s[bc];
    float4 v = x[i];
    v.x = tf32_rna(v.x * s);
    v.y = tf32_rna(v.y * s);
    v.z = tf32_rna(v.z * s);
    v.w = tf32_rna(v.w * s);
    ((float4*)g_xs)[i] = v;
}

// ---------------- main implicit conv (per-batch GEMM, 9 taps per ci-chunk) ----------------
__device__ __forceinline__ void mma_tf32(float* c, uint32_t a0,uint32_t a1,uint32_t a2,uint32_t a3,
                                         uint32_t b0,uint32_t b1){
    asm volatile("mma.sync.aligned.m16n8k8.row.col.f32.tf32.tf32.f32 "
        "{%0,%1,%2,%3}, {%4,%5,%6,%7}, {%8,%9}, {%0,%1,%2,%3};"
        : "+f"(c[0]), "+f"(c[1]), "+f"(c[2]), "+f"(c[3])
        : "r"(a0), "r"(a1), "r"(a2), "r"(a3), "r"(b0), "r"(b1));
}

__global__ __launch_bounds__(256,1) void conv_kernel(float* __restrict__ out){
    extern __shared__ float smem[];
    float* sX = smem;                 // [2][13056]  halo tiles
    float* sW = smem + 2*XH;          // [2][4096]   packed W frags

    const int tid  = threadIdx.x;
    const int lane = tid & 31;
    const int warp = tid >> 5;
    const int wm   = warp >> 2;       // 0..1  (64 out-ch each)
    const int wn   = warp & 3;        // 0..3  (one image row each)
    const int ob = blockIdx.x;        // out-ch block (128)
    const int rt = blockIdx.y;        // row tile (4 rows)
    const int b  = blockIdx.z;        // batch
    const int r0 = rt * 4;

    unsigned sx_u = (unsigned)__cvta_generic_to_shared(sX);
    unsigned sw_u = (unsigned)__cvta_generic_to_shared(sW);

    const float* xg = g_xs + (size_t)b * (CIN*NPIX);

    float acc[4][8][4];
    #pragma unroll
    for (int i=0;i<4;i++)
      #pragma unroll
      for (int j=0;j<8;j++)
        #pragma unroll
        for (int k=0;k<4;k++) acc[i][j][k]=0.f;

    auto load_x = [&](int chunk){
        unsigned sb = sx_u + (unsigned)((chunk & 1) * XH) * 4u;
        const float* gx = xg + chunk * 32 * NPIX;
        for (int i = tid; i < XH; i += 256){
            int ci  = i / XSTR;
            int rem = i - ci * XSTR;
            int r = rem / 68;
            int c = rem - r * 68;
            int grow = r0 - 1 + r;
            int gcol = c - 1;
            bool ok = ((unsigned)grow < 64u) && ((unsigned)gcol < 64u);
            const float* ga = gx + ci * NPIX + (ok ? (grow * 64 + gcol) : 0);
            int sz = ok ? 4 : 0;
            asm volatile("cp.async.ca.shared.global [%0], [%1], 4, %2;"
                         :: "r"(sb + (unsigned)i * 4u), "l"(ga), "r"(sz));
        }
    };

    auto load_w = [&](int step){
        int chunk = step / 9;
        int tap   = step - chunk * 9;
        const float* gw = g_wpack + (((tap*16 + chunk)*4 + ob) << 12);
        unsigned sb = sw_u + (unsigned)((step & 1) * WTILE) * 4u;
        #pragma unroll
        for (int i = 0; i < 4; i++){
            int idx = tid + i * 256;
            asm volatile("cp.async.cg.shared.global [%0], [%1], 16;"
                         :: "r"(sb + (unsigned)idx * 16u), "l"(gw + idx * 4));
        }
    };

    load_x(0);
    load_w(0);
    asm volatile("cp.async.commit_group;");
    asm volatile("cp.async.wait_group 0;");
    __syncthreads();

    for (int step = 0; step < 144; step++){        // 16 ci-chunks * 9 taps
        int chunk = step / 9;
        int tap   = step - chunk * 9;
        if (tap == 0 && chunk < 15) load_x(chunk + 1);
        if (step < 143) load_w(step + 1);
        asm volatile("cp.async.commit_group;");

        const int dh = tap / 3;
        const int dw = tap - dh * 3;
        const float* xb = sX + (chunk & 1) * XH + (wn + dh) * 68 + dw + (lane >> 2);
        const float4* w4 = (const float4*)(sW + (step & 1) * WTILE);

        #pragma unroll
        for (int ks = 0; ks < 4; ks++){
            const float* xp = xb + (ks * 8 + (lane & 3)) * XSTR;
            uint32_t bf[8][2];
            #pragma unroll
            for (int nt = 0; nt < 8; nt++){
                bf[nt][0] = __float_as_uint(xp[nt*8]);
                bf[nt][1] = __float_as_uint(xp[nt*8 + 4*XSTR]);
            }
            #pragma unroll
            for (int mt = 0; mt < 4; mt++){
                float4 a = w4[(ks*8 + wm*4 + mt)*32 + lane];
                uint32_t a0=__float_as_uint(a.x), a1=__float_as_uint(a.y),
                         a2=__float_as_uint(a.z), a3=__float_as_uint(a.w);
                #pragma unroll
                for (int nt = 0; nt < 8; nt++)
                    mma_tf32(acc[mt][nt], a0,a1,a2,a3, bf[nt][0], bf[nt][1]);
            }
        }
        asm volatile("cp.async.wait_group 0;");
        __syncthreads();
    }

    // epilogue: scale by dscale[b][o] and store
    const int rowpx = (r0 + wn) * 64;
    #pragma unroll
    for (int mt = 0; mt < 4; mt++){
        int o0 = ob*128 + wm*64 + mt*16 + (lane >> 2);
        float d0 = g_dscale[b*512 + o0];
        float d1 = g_dscale[b*512 + o0 + 8];
        float* p0 = out + (size_t)(b*512 + o0) * NPIX + rowpx + (lane & 3)*2;
        float* p1 = p0 + (size_t)8 * NPIX;
        #pragma unroll
        for (int nt = 0; nt < 8; nt++){
            float2 v0 = make_float2(acc[mt][nt][0]*d0, acc[mt][nt][1]*d0);
            float2 v1 = make_float2(acc[mt][nt][2]*d1, acc[mt][nt][3]*d1);
            *(float2*)(p0 + nt*8) = v0;
            *(float2*)(p1 + nt*8) = v1;
        }
    }
}

// ---------------- launcher ----------------
extern "C" void kernel_launch(void* const* d_in, const int* in_sizes, int n_in,
                              void* d_out, int out_size){
    const float* input      = (const float*)d_in[0];
    const float* style      = (const float*)d_in[1];
    const float* weight     = (const float*)d_in[2];
    const float* mod_weight = (const float*)d_in[3];
    const float* mod_bias   = (const float*)d_in[4];
    float* out = (float*)d_out;

    cudaFuncSetAttribute(conv_kernel, cudaFuncAttributeMaxDynamicSharedMemorySize, CONV_SMEM);

    mod_kernel   <<<16, 512>>>(style, mod_weight, mod_bias);
    wsq_kernel   <<<1024, 256>>>(weight);
    demod_kernel <<<16, 512>>>();
    pack_kernel  <<<9216, 256>>>(weight);
    xscale_kernel<<<8192, 1024>>>((const float4*)input);
    conv_kernel  <<<dim3(4,16,16), 256, CONV_SMEM>>>(out);
}

// round 7
// speedup vs baseline: 1.6184x; 1.6166x over previous
#include <cuda_runtime.h>
#include <cuda_fp16.h>
#include <cstdint>
#include <cstddef>

#define BATCH 16
#define CIN   512
#define COUT  512
#define NPIX  4096
#define MOD_SCALE  0.044194173824159216f
#define CONV_SCALE 0.014731391274719739f

#define PLANE_W 4488      // words per pair-plane (66 rows * 68 cols), 1 word = f16x2 (ci pair)
#define HALO_W  6528      // words per halo buffer: 16 pairs * 6 rows * 68 cols
#define HALO_B  26112
#define WTILE_B 8192      // 128 o * 32 ci * 2B
#define CONV_SMEM (2*HALO_B + 2*WTILE_B)   // 68608 bytes

// ---------------- device scratch ----------------
__device__ float g_s[BATCH*CIN];
__device__ float g_wsq[COUT*CIN];
__device__ float g_dscale[BATCH*COUT];
__device__ __align__(128) __half   g_wpack[4*144*4096];               // 4.7 MB, frag-packed fp16
__device__ __align__(128) uint32_t g_xs[(size_t)BATCH*256*PLANE_W];   // 73.5 MB padded pair-planes

// ---------------- s[b][ci] = style @ (mod_weight*MOD_SCALE)^T + bias ----------------
__global__ void mod_kernel(const float* __restrict__ style,
                           const float* __restrict__ mod_weight,
                           const float* __restrict__ mod_bias){
    __shared__ float st[512];
    int b = blockIdx.x, t = threadIdx.x;
    st[t] = style[b*512 + t];
    __syncthreads();
    const float* wr = mod_weight + t*512;
    float acc = 0.f;
    #pragma unroll 8
    for (int j = 0; j < 512; j++) acc = fmaf(st[j], wr[j], acc);
    g_s[b*512 + t] = acc * MOD_SCALE + mod_bias[t];
}

// ---------------- wsq[o][ci] = sum_t weight^2 ----------------
__global__ void wsq_kernel(const float* __restrict__ w){
    int i = blockIdx.x*blockDim.x + threadIdx.x;   // 262144
    const float* p = w + i*9;
    float a = 0.f;
    #pragma unroll
    for (int t = 0; t < 9; t++) a = fmaf(p[t], p[t], a);
    g_wsq[i] = a;
}

// ---------------- dscale[b][o] = CONV_SCALE * rsqrt(CONV_SCALE^2 * sum s^2*wsq + 1e-8) ----------------
__global__ void demod_kernel(){
    __shared__ float s2[512];
    int b = blockIdx.x, t = threadIdx.x;
    float sv = g_s[b*512 + t];
    s2[t] = sv*sv;
    __syncthreads();
    const float* wr = g_wsq + t*512;
    float acc = 0.f;
    #pragma unroll 8
    for (int j = 0; j < 512; j++) acc = fmaf(s2[j], wr[j], acc);
    float v = CONV_SCALE*CONV_SCALE*acc + 1e-8f;
    g_dscale[b*512 + t] = CONV_SCALE / sqrtf(v);
}

// ---------------- pack W into m16n8k16 fragment layout, fp16 ----------------
// layout: [ob][unit=chunk*9+tap][ks(2)][mtile(8)][lane(32)][8 halves = regs r0..r3 as f16x2]
// A-frag (row-major 16x16): r0=(m, k0k1) r1=(m+8, k0k1) r2=(m, k8k9) r3=(m+8, k8k9),
//   m = lane>>2, k0 = (lane&3)*2 within the ks-th k16 block.
__global__ void pack_kernel(const float* __restrict__ w){
    int i = blockIdx.x*256 + threadIdx.x;          // 2359296 = 512*512*9, coalesced read
    int o   = i / 4608;
    int rem = i - o*4608;
    int ci  = rem / 9;
    int tap = rem - ci*9;
    int unit = (ci >> 5)*9 + tap;
    int c  = ci & 31;
    int ks = c >> 4, cc = c & 15;
    int lane = (o & 7)*4 + ((cc >> 1) & 3);
    int r    = ((o >> 3) & 1) + ((cc >> 3) & 1)*2;
    int mtile = (o >> 4) & 7;
    int ob    = o >> 7;
    size_t off = (((size_t)(ob*144 + unit)) << 12)
               + (size_t)(((ks*8 + mtile)*32 + lane) << 3) + r*2 + (cc & 1);
    g_wpack[off] = __float2half_rn(w[i]);
}

// ---------------- xs: padded 66x68 pair-planes, fp16x2 (ci even in low half) ----------------
__global__ void xscale_kernel(const float* __restrict__ x){
    size_t i = (size_t)blockIdx.x*256 + threadIdx.x;   // 18,382,848 words
    int bc  = (int)(i / PLANE_W);                      // b*256 + cipair
    int rem = (int)(i - (size_t)bc*PLANE_W);
    int pr = rem / 68;
    int pc = rem - pr*68;
    int r = pr - 1, cc = pc - 1;
    uint32_t v = 0;
    if ((unsigned)r < 64u && (unsigned)cc < 64u){
        int b = bc >> 8, cp = bc & 255;
        const float* xp = x + ((size_t)(b*512 + cp*2))*NPIX + r*64 + cc;
        float s0 = g_s[b*512 + cp*2];
        float s1 = g_s[b*512 + cp*2 + 1];
        __half h0 = __float2half_rn(xp[0]    * s0);
        __half h1 = __float2half_rn(xp[NPIX] * s1);
        v = (uint32_t)__half_as_ushort(h0) | ((uint32_t)__half_as_ushort(h1) << 16);
    }
    g_xs[i] = v;
}

// ---------------- main implicit conv (fp16 m16n8k16) ----------------
__device__ __forceinline__ void mma_f16(float* c, uint32_t a0,uint32_t a1,uint32_t a2,uint32_t a3,
                                        uint32_t b0,uint32_t b1){
    asm volatile("mma.sync.aligned.m16n8k16.row.col.f32.f16.f16.f32 "
        "{%0,%1,%2,%3}, {%4,%5,%6,%7}, {%8,%9}, {%0,%1,%2,%3};"
        : "+f"(c[0]), "+f"(c[1]), "+f"(c[2]), "+f"(c[3])
        : "r"(a0), "r"(a1), "r"(a2), "r"(a3), "r"(b0), "r"(b1));
}

__global__ __launch_bounds__(256,1) void conv_kernel(float* __restrict__ out){
    extern __shared__ char smem[];
    uint32_t* sX = (uint32_t*)smem;                       // [2][6528] f16x2 words
    const float4* sW = (const float4*)(smem + 2*HALO_B);  // [2][512] 16B frags

    const int tid  = threadIdx.x;
    const int lane = tid & 31;
    const int warp = tid >> 5;
    const int wm   = warp >> 2;       // 0..1  (64 out-ch each)
    const int wn   = warp & 3;        // 0..3  (one image row each)
    const int ob = blockIdx.x;        // out-ch block (128)
    const int rt = blockIdx.y;        // row tile (4 rows)
    const int b  = blockIdx.z;        // batch
    const int r0 = rt * 4;

    unsigned sx_u = (unsigned)__cvta_generic_to_shared(smem);
    unsigned sw_u = sx_u + 2*HALO_B;

    // gmem source: pair-plane uint4 chunks; halo slab (6 rows) is contiguous per pair
    const uint4* gx = (const uint4*)g_xs + (size_t)(b*256)*1122 + rt*68;

    float acc[4][8][4];
    #pragma unroll
    for (int i=0;i<4;i++)
      #pragma unroll
      for (int j=0;j<8;j++)
        #pragma unroll
        for (int k=0;k<4;k++) acc[i][j][k]=0.f;

    auto load_x = [&](int chunk){
        unsigned sb = sx_u + (unsigned)((chunk & 1) * HALO_B);
        const uint4* src = gx + (size_t)chunk * 16 * 1122;
        for (int i = tid; i < 1632; i += 256){            // 16 pairs * 102 chunks
            int cp = i / 102, j = i - cp * 102;
            asm volatile("cp.async.cg.shared.global [%0], [%1], 16;"
                         :: "r"(sb + (unsigned)(cp*1632 + j*16)),
                            "l"(src + (size_t)cp*1122 + j));
        }
    };

    auto load_w = [&](int step){
        const uint4* wsrc = (const uint4*)g_wpack + (size_t)(ob*144 + step) * 512;
        unsigned sb = sw_u + (unsigned)((step & 1) * WTILE_B);
        #pragma unroll
        for (int i = 0; i < 2; i++){
            int idx = tid + i * 256;
            asm volatile("cp.async.cg.shared.global [%0], [%1], 16;"
                         :: "r"(sb + (unsigned)idx * 16u), "l"(wsrc + idx));
        }
    };

    load_x(0);
    load_w(0);
    asm volatile("cp.async.commit_group;");
    asm volatile("cp.async.wait_group 0;");
    __syncthreads();

    for (int step = 0; step < 144; step++){        // 16 ci-chunks * 9 taps
        int chunk = step / 9;
        int tap   = step - chunk * 9;
        if (tap == 0 && chunk < 15) load_x(chunk + 1);
        if (step < 143) load_w(step + 1);
        asm volatile("cp.async.commit_group;");

        const int dh = tap / 3;
        const int dw = tap - dh * 3;
        const uint32_t* xb = sX + (chunk & 1) * HALO_W + (wn + dh) * 68 + dw + (lane >> 2);
        const float4* w4 = sW + (step & 1) * 512;

        #pragma unroll
        for (int ks = 0; ks < 2; ks++){
            // b0: ci pair (2k,2k+1) at cipair = ks*8 + lane%4 ; b1: +4 pairs (ci+8)
            const uint32_t* xp = xb + (ks * 8 + (lane & 3)) * 408;
            uint32_t bf[8][2];
            #pragma unroll
            for (int nt = 0; nt < 8; nt++){
                bf[nt][0] = xp[nt*8];
                bf[nt][1] = xp[nt*8 + 4*408];
            }
            #pragma unroll
            for (int mt = 0; mt < 4; mt++){
                float4 a = w4[(ks*8 + wm*4 + mt)*32 + lane];
                uint32_t a0=__float_as_uint(a.x), a1=__float_as_uint(a.y),
                         a2=__float_as_uint(a.z), a3=__float_as_uint(a.w);
                #pragma unroll
                for (int nt = 0; nt < 8; nt++)
                    mma_f16(acc[mt][nt], a0,a1,a2,a3, bf[nt][0], bf[nt][1]);
            }
        }
        asm volatile("cp.async.wait_group 0;");
        __syncthreads();
    }

    // epilogue: scale by dscale[b][o] and store (C layout identical to k8 case)
    const int rowpx = (r0 + wn) * 64;
    #pragma unroll
    for (int mt = 0; mt < 4; mt++){
        int o0 = ob*128 + wm*64 + mt*16 + (lane >> 2);
        float d0 = g_dscale[b*512 + o0];
        float d1 = g_dscale[b*512 + o0 + 8];
        float* p0 = out + (size_t)(b*512 + o0) * NPIX + rowpx + (lane & 3)*2;
        float* p1 = p0 + (size_t)8 * NPIX;
        #pragma unroll
        for (int nt = 0; nt < 8; nt++){
            float2 v0 = make_float2(acc[mt][nt][0]*d0, acc[mt][nt][1]*d0);
            float2 v1 = make_float2(acc[mt][nt][2]*d1, acc[mt][nt][3]*d1);
            *(float2*)(p0 + nt*8) = v0;
            *(float2*)(p1 + nt*8) = v1;
        }
    }
}

// ---------------- launcher ----------------
extern "C" void kernel_launch(void* const* d_in, const int* in_sizes, int n_in,
                              void* d_out, int out_size){
    const float* input      = (const float*)d_in[0];
    const float* style      = (const float*)d_in[1];
    const float* weight     = (const float*)d_in[2];
    const float* mod_weight = (const float*)d_in[3];
    const float* mod_bias   = (const float*)d_in[4];
    float* out = (float*)d_out;

    cudaFuncSetAttribute(conv_kernel, cudaFuncAttributeMaxDynamicSharedMemorySize, CONV_SMEM);

    mod_kernel   <<<16, 512>>>(style, mod_weight, mod_bias);
    wsq_kernel   <<<1024, 256>>>(weight);
    demod_kernel <<<16, 512>>>();
    pack_kernel  <<<9216, 256>>>(weight);
    xscale_kernel<<<71808, 256>>>(input);
    conv_kernel  <<<dim3(4,16,16), 256, CONV_SMEM>>>(out);
}

// round 8
// speedup vs baseline: 1.9569x; 1.2092x over previous
#include <cuda_runtime.h>
#include <cuda_fp16.h>
#include <cstdint>
#include <cstddef>

#define BATCH 16
#define CIN   512
#define COUT  512
#define NPIX  4096
#define MOD_SCALE  0.044194173824159216f
#define CONV_SCALE 0.014731391274719739f

// Winograd F(2x2,3x3): 32x32=1024 output tiles per image, 16 transform points (u)
// GEMM per (u,b): M_u[512co, 1024t] = W_u[512co,512ci] * D_u[512ci,1024t]

// GEMM smem: D chunk [16 cipair][264 words] x2 + W chunk [512 uint4 halves] x2
#define DSTR   264
#define DCH_W  (16*DSTR)            // 4224 words per buffer
#define GEMM_SMEM (2*DCH_W*4 + 2*8192)   // 33792 + 16384 = 50176 B

// ---------------- device scratch ----------------
__device__ float g_s[BATCH*CIN];
__device__ float g_wsq[COUT*CIN];
__device__ float g_dscale[BATCH*COUT];
__device__ __align__(128) __half   g_wg[16*4*16*4096];                 // 8 MB transformed W, frag-packed
__device__ __align__(128) uint32_t g_d[(size_t)16*16*256*1024];        // 268 MB transformed input (f16x2 ci-pairs)
__device__ __align__(128) __half   g_m[(size_t)16*16*512*1024];        // 268 MB GEMM output M

// ---------------- s[b][ci] = style @ (mod_weight*MOD_SCALE)^T + bias ----------------
__global__ void mod_kernel(const float* __restrict__ style,
                           const float* __restrict__ mod_weight,
                           const float* __restrict__ mod_bias){
    __shared__ float st[512];
    int b = blockIdx.x, t = threadIdx.x;
    st[t] = style[b*512 + t];
    __syncthreads();
    const float* wr = mod_weight + t*512;
    float acc = 0.f;
    #pragma unroll 8
    for (int j = 0; j < 512; j++) acc = fmaf(st[j], wr[j], acc);
    g_s[b*512 + t] = acc * MOD_SCALE + mod_bias[t];
}

// ---------------- wsq[o][ci] = sum_t weight^2 ----------------
__global__ void wsq_kernel(const float* __restrict__ w){
    int i = blockIdx.x*blockDim.x + threadIdx.x;   // 262144
    const float* p = w + (size_t)i*9;
    float a = 0.f;
    #pragma unroll
    for (int t = 0; t < 9; t++) a = fmaf(p[t], p[t], a);
    g_wsq[i] = a;
}

// ---------------- dscale[b][o] = CONV_SCALE * rsqrt(CONV_SCALE^2 * sum s^2*wsq + 1e-8) ----------------
__global__ void demod_kernel(){
    __shared__ float s2[512];
    int b = blockIdx.x, t = threadIdx.x;
    float sv = g_s[b*512 + t];
    s2[t] = sv*sv;
    __syncthreads();
    const float* wr = g_wsq + t*512;
    float acc = 0.f;
    #pragma unroll 8
    for (int j = 0; j < 512; j++) acc = fmaf(s2[j], wr[j], acc);
    float v = CONV_SCALE*CONV_SCALE*acc + 1e-8f;
    g_dscale[b*512 + t] = CONV_SCALE / sqrtf(v);
}

// ---------------- weight transform: U = G g G^T, frag-packed fp16 ----------------
// g_wg layout: [u][cb(4)][kc(16)] tile of 4096 halves: [ks(2)][mt(8)][lane(32)][r(4) x f16x2]
__global__ void wtrans_kernel(const float* __restrict__ w){
    int i = blockIdx.x*256 + threadIdx.x;          // 262144 = co*512+ci
    int co = i >> 9, ci = i & 511;
    const float* p = w + (size_t)i*9;
    float g[3][3];
    #pragma unroll
    for (int r = 0; r < 3; r++)
        #pragma unroll
        for (int c = 0; c < 3; c++) g[r][c] = p[r*3+c];
    float t[4][3];
    #pragma unroll
    for (int c = 0; c < 3; c++){
        t[0][c] = g[0][c];
        t[1][c] = 0.5f*(g[0][c]+g[1][c]+g[2][c]);
        t[2][c] = 0.5f*(g[0][c]-g[1][c]+g[2][c]);
        t[3][c] = g[2][c];
    }
    float U[16];
    #pragma unroll
    for (int r = 0; r < 4; r++){
        U[r*4+0] = t[r][0];
        U[r*4+1] = 0.5f*(t[r][0]+t[r][1]+t[r][2]);
        U[r*4+2] = 0.5f*(t[r][0]-t[r][1]+t[r][2]);
        U[r*4+3] = t[r][2];
    }
    int kc = ci>>5, c5 = ci&31, ks = c5>>4, cc = c5&15;
    int lane = (co&7)*4 + ((cc>>1)&3);
    int r    = ((co>>3)&1) + ((cc>>3)&1)*2;
    int mt   = (co>>4)&7, cb = co>>7;
    size_t boff = ((size_t)(cb*16 + kc))*4096 + (size_t)(((ks*8+mt)*32+lane)<<3) + r*2 + (cc&1);
    #pragma unroll
    for (int u = 0; u < 16; u++)
        g_wg[boff + (size_t)u*262144] = __float2half_rn(U[u]);
}

// ---------------- input transform: D = B^T (s*x) B, fused s-scale ----------------
// g_d word layout: [b][u][cipair(256)][tile(1024)], word = f16x2 (ci even, ci odd)
__global__ void dtrans_kernel(const float* __restrict__ x){
    __shared__ float2 spad[66*66];
    int cp = blockIdx.x, b = blockIdx.y, tid = threadIdx.x;
    const float* x0 = x + ((size_t)(b*512 + cp*2))*NPIX;
    const float* x1 = x0 + NPIX;
    float s0 = g_s[b*512 + cp*2];
    float s1 = g_s[b*512 + cp*2 + 1];
    for (int idx = tid; idx < 66*66; idx += 256){
        int r = idx / 66, c = idx - r*66;
        int ir = r - 1, ic = c - 1;
        float2 v = make_float2(0.f, 0.f);
        if ((unsigned)ir < 64u && (unsigned)ic < 64u){
            v.x = x0[ir*64 + ic] * s0;
            v.y = x1[ir*64 + ic] * s1;
        }
        spad[idx] = v;
    }
    __syncthreads();
    #pragma unroll
    for (int tt = 0; tt < 4; tt++){
        int tile = tid + tt*256;
        int i = tile >> 5, j = tile & 31;
        float2 d[4][4];
        #pragma unroll
        for (int rr = 0; rr < 4; rr++)
            #pragma unroll
            for (int cc = 0; cc < 4; cc++) d[rr][cc] = spad[(2*i+rr)*66 + 2*j+cc];
        float u0[16], u1[16];
        {
            float t[4][4];
            #pragma unroll
            for (int c = 0; c < 4; c++){
                t[0][c] = d[0][c].x - d[2][c].x;
                t[1][c] = d[1][c].x + d[2][c].x;
                t[2][c] = d[2][c].x - d[1][c].x;
                t[3][c] = d[1][c].x - d[3][c].x;
            }
            #pragma unroll
            for (int r = 0; r < 4; r++){
                u0[r*4+0] = t[r][0] - t[r][2];
                u0[r*4+1] = t[r][1] + t[r][2];
                u0[r*4+2] = t[r][2] - t[r][1];
                u0[r*4+3] = t[r][1] - t[r][3];
            }
        }
        {
            float t[4][4];
            #pragma unroll
            for (int c = 0; c < 4; c++){
                t[0][c] = d[0][c].y - d[2][c].y;
                t[1][c] = d[1][c].y + d[2][c].y;
                t[2][c] = d[2][c].y - d[1][c].y;
                t[3][c] = d[1][c].y - d[3][c].y;
            }
            #pragma unroll
            for (int r = 0; r < 4; r++){
                u1[r*4+0] = t[r][0] - t[r][2];
                u1[r*4+1] = t[r][1] + t[r][2];
                u1[r*4+2] = t[r][2] - t[r][1];
                u1[r*4+3] = t[r][1] - t[r][3];
            }
        }
        #pragma unroll
        for (int u = 0; u < 16; u++){
            __half2 h = __floats2half2_rn(u0[u], u1[u]);
            g_d[((size_t)(b*16+u)*256 + cp)*1024 + tile] = *(uint32_t*)&h;
        }
    }
}

// ---------------- GEMM: M_u[b] = W_u @ D_u[b], fp16 m16n8k16, fp32 accum ----------------
__device__ __forceinline__ void mma_f16(float* c, uint32_t a0,uint32_t a1,uint32_t a2,uint32_t a3,
                                        uint32_t b0,uint32_t b1){
    asm volatile("mma.sync.aligned.m16n8k16.row.col.f32.f16.f16.f32 "
        "{%0,%1,%2,%3}, {%4,%5,%6,%7}, {%8,%9}, {%0,%1,%2,%3};"
        : "+f"(c[0]), "+f"(c[1]), "+f"(c[2]), "+f"(c[3])
        : "r"(a0), "r"(a1), "r"(a2), "r"(a3), "r"(b0), "r"(b1));
}

__global__ __launch_bounds__(256,1) void gemm_kernel(){
    extern __shared__ char smem[];
    uint32_t* sD = (uint32_t*)smem;                       // [2][4224] f16x2 words
    const float4* sW = (const float4*)(smem + 2*DCH_W*4); // [2][512] 16B A-frags

    const int tid  = threadIdx.x;
    const int lane = tid & 31;
    const int warp = tid >> 5;
    const int wm   = warp >> 2;       // co half (64)
    const int wn   = warp & 3;        // tile quarter (64)
    const int cb = blockIdx.x >> 2;   // co block (128)
    const int nb = blockIdx.x & 3;    // tile block (256)
    const int u  = blockIdx.y;
    const int b  = blockIdx.z;
    const int tile0 = nb * 256;

    unsigned sd_u = (unsigned)__cvta_generic_to_shared(smem);
    unsigned sw_u = sd_u + 2*DCH_W*4;

    const uint4* dsrc = (const uint4*)g_d + (size_t)(b*16+u)*65536 + (tile0 >> 2);
    const uint4* wsrc = (const uint4*)g_wg + (size_t)(u*4+cb)*8192;

    float acc[4][8][4];
    #pragma unroll
    for (int i=0;i<4;i++)
      #pragma unroll
      for (int j=0;j<8;j++)
        #pragma unroll
        for (int k=0;k<4;k++) acc[i][j][k]=0.f;

    auto load = [&](int kc){
        unsigned db = sd_u + (unsigned)((kc & 1) * DCH_W * 4);
        #pragma unroll
        for (int k = 0; k < 4; k++){
            int i = tid + k*256;
            int cp = i >> 6, q = i & 63;
            asm volatile("cp.async.cg.shared.global [%0], [%1], 16;"
                         :: "r"(db + (unsigned)((cp*DSTR + q*4)*4)),
                            "l"(dsrc + (size_t)(kc*16 + cp)*256 + q));
        }
        unsigned wb = sw_u + (unsigned)((kc & 1) * 8192);
        #pragma unroll
        for (int k = 0; k < 2; k++){
            int i = tid + k*256;
            asm volatile("cp.async.cg.shared.global [%0], [%1], 16;"
                         :: "r"(wb + (unsigned)(i*16)), "l"(wsrc + kc*512 + i));
        }
    };

    load(0);
    asm volatile("cp.async.commit_group;");
    asm volatile("cp.async.wait_group 0;");
    __syncthreads();

    for (int kc = 0; kc < 16; kc++){
        if (kc < 15) load(kc + 1);
        asm volatile("cp.async.commit_group;");

        const uint32_t* xb = sD + (kc & 1)*DCH_W + wn*64 + (lane >> 2);
        const float4* w4 = sW + (kc & 1)*512;

        #pragma unroll
        for (int ks = 0; ks < 2; ks++){
            const uint32_t* xp = xb + (ks*8 + (lane & 3)) * DSTR;
            uint32_t bf[8][2];
            #pragma unroll
            for (int nt = 0; nt < 8; nt++){
                bf[nt][0] = xp[nt*8];
                bf[nt][1] = xp[nt*8 + 4*DSTR];
            }
            #pragma unroll
            for (int mt = 0; mt < 4; mt++){
                float4 a = w4[(ks*8 + wm*4 + mt)*32 + lane];
                uint32_t a0=__float_as_uint(a.x), a1=__float_as_uint(a.y),
                         a2=__float_as_uint(a.z), a3=__float_as_uint(a.w);
                #pragma unroll
                for (int nt = 0; nt < 8; nt++)
                    mma_f16(acc[mt][nt], a0,a1,a2,a3, bf[nt][0], bf[nt][1]);
            }
        }
        asm volatile("cp.async.wait_group 0;");
        __syncthreads();
    }

    // epilogue: write M as fp16
    #pragma unroll
    for (int mt = 0; mt < 4; mt++){
        int co = cb*128 + wm*64 + mt*16 + (lane >> 2);
        size_t rb = ((size_t)(b*16+u)*512 + co)*1024;
        #pragma unroll
        for (int nt = 0; nt < 8; nt++){
            int tile = tile0 + wn*64 + nt*8 + (lane & 3)*2;
            __half2 v0 = __floats2half2_rn(acc[mt][nt][0], acc[mt][nt][1]);
            __half2 v1 = __floats2half2_rn(acc[mt][nt][2], acc[mt][nt][3]);
            *(__half2*)(g_m + rb + tile)            = v0;
            *(__half2*)(g_m + rb + 8*1024 + tile)   = v1;
        }
    }
}

// ---------------- inverse transform: out = A^T M A * dscale ----------------
__global__ void inv_kernel(float* __restrict__ out){
    int co = blockIdx.x, b = blockIdx.y, tid = threadIdx.x;
    float ds = g_dscale[b*512 + co];
    const __half* mp = g_m + ((size_t)(b*16)*512 + co)*1024;   // + u*524288 + tile
    float* op = out + ((size_t)(b*512 + co))*NPIX;
    #pragma unroll
    for (int tt = 0; tt < 4; tt++){
        int tile = tid + tt*256;
        int i = tile >> 5, j = tile & 31;
        float m[16];
        #pragma unroll
        for (int u = 0; u < 16; u++)
            m[u] = __half2float(mp[(size_t)u*524288 + tile]);
        float p0[4], p1[4];
        #pragma unroll
        for (int c = 0; c < 4; c++){
            p0[c] = m[c] + m[4+c] + m[8+c];
            p1[c] = m[4+c] - m[8+c] - m[12+c];
        }
        float o00 = p0[0]+p0[1]+p0[2], o01 = p0[1]-p0[2]-p0[3];
        float o10 = p1[0]+p1[1]+p1[2], o11 = p1[1]-p1[2]-p1[3];
        *(float2*)(op + (2*i)*64   + 2*j) = make_float2(o00*ds, o01*ds);
        *(float2*)(op + (2*i+1)*64 + 2*j) = make_float2(o10*ds, o11*ds);
    }
}

// ---------------- launcher ----------------
extern "C" void kernel_launch(void* const* d_in, const int* in_sizes, int n_in,
                              void* d_out, int out_size){
    const float* input      = (const float*)d_in[0];
    const float* style      = (const float*)d_in[1];
    const float* weight     = (const float*)d_in[2];
    const float* mod_weight = (const float*)d_in[3];
    const float* mod_bias   = (const float*)d_in[4];
    float* out = (float*)d_out;

    cudaFuncSetAttribute(gemm_kernel, cudaFuncAttributeMaxDynamicSharedMemorySize, GEMM_SMEM);

    mod_kernel    <<<16, 512>>>(style, mod_weight, mod_bias);
    wsq_kernel    <<<1024, 256>>>(weight);
    demod_kernel  <<<16, 512>>>();
    wtrans_kernel <<<1024, 256>>>(weight);
    dtrans_kernel <<<dim3(256,16), 256>>>(input);
    gemm_kernel   <<<dim3(16,16,16), 256, GEMM_SMEM>>>();
    inv_kernel    <<<dim3(512,16), 256>>>(out);
}

// round 9
// speedup vs baseline: 2.2454x; 1.1474x over previous
#include <cuda_runtime.h>
#include <cuda_fp16.h>
#include <cstdint>
#include <cstddef>

#define BATCH 16
#define CIN   512
#define COUT  512
#define NPIX  4096
#define MOD_SCALE  0.044194173824159216f
#define CONV_SCALE 0.014731391274719739f

// Winograd F(2x2,3x3): 1024 tiles/image, 16 transform points (u)
// GEMM per (u,b): M_u[512co,1024t] = W_u[512co,512ci] * D_u[512ci,1024t]
// CTA tile: 128co x 128t, K-chunk 32ci, 3-stage cp.async, 2 CTAs/SM

#define DSTR   136                          // 128 tiles + 8 pad words (8 mod 32 -> conflict-free)
#define DCH_B  (16*DSTR*4)                  // 8704 B per D stage
#define STAGE_B (DCH_B + 8192)              // 16896 B (D + W)
#define GEMM_SMEM (3*STAGE_B)               // 50688 B

// ---------------- device scratch ----------------
__device__ float g_s[BATCH*CIN];
__device__ float g_wsq[COUT*CIN];
__device__ float g_dscale[BATCH*COUT];
__device__ __align__(128) __half   g_wg[16*4*16*4096];                 // 8 MB transformed W, frag-packed
__device__ __align__(128) uint32_t g_d[(size_t)16*16*256*1024];        // 268 MB transformed input (f16x2 ci-pairs)
__device__ __align__(128) __half   g_m[(size_t)16*16*512*1024];        // 268 MB GEMM output M

// ---------------- s[b][ci] = style @ (mod_weight*MOD_SCALE)^T + bias ----------------
__global__ void mod_kernel(const float* __restrict__ style,
                           const float* __restrict__ mod_weight,
                           const float* __restrict__ mod_bias){
    __shared__ float st[512];
    int b = blockIdx.x, t = threadIdx.x;
    st[t] = style[b*512 + t];
    __syncthreads();
    const float* wr = mod_weight + t*512;
    float acc = 0.f;
    #pragma unroll 8
    for (int j = 0; j < 512; j++) acc = fmaf(st[j], wr[j], acc);
    g_s[b*512 + t] = acc * MOD_SCALE + mod_bias[t];
}

// ---------------- dscale[b][o] = CONV_SCALE * rsqrt(CONV_SCALE^2 * sum s^2*wsq + 1e-8) ----------------
__global__ void demod_kernel(){
    __shared__ float s2[512];
    int b = blockIdx.x, t = threadIdx.x;
    float sv = g_s[b*512 + t];
    s2[t] = sv*sv;
    __syncthreads();
    const float* wr = g_wsq + t*512;
    float acc = 0.f;
    #pragma unroll 8
    for (int j = 0; j < 512; j++) acc = fmaf(s2[j], wr[j], acc);
    float v = CONV_SCALE*CONV_SCALE*acc + 1e-8f;
    g_dscale[b*512 + t] = CONV_SCALE / sqrtf(v);
}

// ---------------- weight transform U = G g G^T (frag-packed fp16) + fused wsq ----------------
// g_wg layout: [u][cb(4)][kc(16)] tile of 4096 halves: [ks(2)][mt(8)][lane(32)][r(4) x f16x2]
__global__ void wtrans_kernel(const float* __restrict__ w){
    int i = blockIdx.x*256 + threadIdx.x;          // 262144 = co*512+ci
    int co = i >> 9, ci = i & 511;
    const float* p = w + (size_t)i*9;
    float g[3][3];
    float sq = 0.f;
    #pragma unroll
    for (int r = 0; r < 3; r++)
        #pragma unroll
        for (int c = 0; c < 3; c++){ g[r][c] = p[r*3+c]; sq = fmaf(g[r][c], g[r][c], sq); }
    g_wsq[i] = sq;
    float t[4][3];
    #pragma unroll
    for (int c = 0; c < 3; c++){
        t[0][c] = g[0][c];
        t[1][c] = 0.5f*(g[0][c]+g[1][c]+g[2][c]);
        t[2][c] = 0.5f*(g[0][c]-g[1][c]+g[2][c]);
        t[3][c] = g[2][c];
    }
    float U[16];
    #pragma unroll
    for (int r = 0; r < 4; r++){
        U[r*4+0] = t[r][0];
        U[r*4+1] = 0.5f*(t[r][0]+t[r][1]+t[r][2]);
        U[r*4+2] = 0.5f*(t[r][0]-t[r][1]+t[r][2]);
        U[r*4+3] = t[r][2];
    }
    int kc = ci>>5, c5 = ci&31, ks = c5>>4, cc = c5&15;
    int lane = (co&7)*4 + ((cc>>1)&3);
    int r    = ((co>>3)&1) + ((cc>>3)&1)*2;
    int mt   = (co>>4)&7, cb = co>>7;
    size_t boff = ((size_t)(cb*16 + kc))*4096 + (size_t)(((ks*8+mt)*32+lane)<<3) + r*2 + (cc&1);
    #pragma unroll
    for (int u = 0; u < 16; u++)
        g_wg[boff + (size_t)u*262144] = __float2half_rn(U[u]);
}

// ---------------- input transform: D = B^T (s*x) B, fused s-scale ----------------
// g_d word layout: [b][u][cipair(256)][tile(1024)], word = f16x2 (ci even, ci odd)
__global__ void dtrans_kernel(const float* __restrict__ x){
    __shared__ float2 spad[66*66];
    int cp = blockIdx.x, b = blockIdx.y, tid = threadIdx.x;
    const float* x0 = x + ((size_t)(b*512 + cp*2))*NPIX;
    const float* x1 = x0 + NPIX;
    float s0 = g_s[b*512 + cp*2];
    float s1 = g_s[b*512 + cp*2 + 1];
    for (int idx = tid; idx < 66*66; idx += 256){
        int r = idx / 66, c = idx - r*66;
        int ir = r - 1, ic = c - 1;
        float2 v = make_float2(0.f, 0.f);
        if ((unsigned)ir < 64u && (unsigned)ic < 64u){
            v.x = x0[ir*64 + ic] * s0;
            v.y = x1[ir*64 + ic] * s1;
        }
        spad[idx] = v;
    }
    __syncthreads();
    #pragma unroll
    for (int tt = 0; tt < 4; tt++){
        int tile = tid + tt*256;
        int i = tile >> 5, j = tile & 31;
        float2 d[4][4];
        #pragma unroll
        for (int rr = 0; rr < 4; rr++)
            #pragma unroll
            for (int cc = 0; cc < 4; cc++) d[rr][cc] = spad[(2*i+rr)*66 + 2*j+cc];
        float u0[16], u1[16];
        {
            float t[4][4];
            #pragma unroll
            for (int c = 0; c < 4; c++){
                t[0][c] = d[0][c].x - d[2][c].x;
                t[1][c] = d[1][c].x + d[2][c].x;
                t[2][c] = d[2][c].x - d[1][c].x;
                t[3][c] = d[1][c].x - d[3][c].x;
            }
            #pragma unroll
            for (int r = 0; r < 4; r++){
                u0[r*4+0] = t[r][0] - t[r][2];
                u0[r*4+1] = t[r][1] + t[r][2];
                u0[r*4+2] = t[r][2] - t[r][1];
                u0[r*4+3] = t[r][1] - t[r][3];
            }
        }
        {
            float t[4][4];
            #pragma unroll
            for (int c = 0; c < 4; c++){
                t[0][c] = d[0][c].y - d[2][c].y;
                t[1][c] = d[1][c].y + d[2][c].y;
                t[2][c] = d[2][c].y - d[1][c].y;
                t[3][c] = d[1][c].y - d[3][c].y;
            }
            #pragma unroll
            for (int r = 0; r < 4; r++){
                u1[r*4+0] = t[r][0] - t[r][2];
                u1[r*4+1] = t[r][1] + t[r][2];
                u1[r*4+2] = t[r][2] - t[r][1];
                u1[r*4+3] = t[r][1] - t[r][3];
            }
        }
        #pragma unroll
        for (int u = 0; u < 16; u++){
            __half2 h = __floats2half2_rn(u0[u], u1[u]);
            g_d[((size_t)(b*16+u)*256 + cp)*1024 + tile] = *(uint32_t*)&h;
        }
    }
}

// ---------------- GEMM: fp16 m16n8k16, fp32 accum, 128co x 128t, occ 2, 3-stage ----------------
__device__ __forceinline__ void mma_f16(float* c, uint32_t a0,uint32_t a1,uint32_t a2,uint32_t a3,
                                        uint32_t b0,uint32_t b1){
    asm volatile("mma.sync.aligned.m16n8k16.row.col.f32.f16.f16.f32 "
        "{%0,%1,%2,%3}, {%4,%5,%6,%7}, {%8,%9}, {%0,%1,%2,%3};"
        : "+f"(c[0]), "+f"(c[1]), "+f"(c[2]), "+f"(c[3])
        : "r"(a0), "r"(a1), "r"(a2), "r"(a3), "r"(b0), "r"(b1));
}

__global__ __launch_bounds__(256,2) void gemm_kernel(){
    extern __shared__ char smem[];
    const int tid  = threadIdx.x;
    const int lane = tid & 31;
    const int warp = tid >> 5;
    const int wm   = warp >> 2;       // co half (64)
    const int wn   = warp & 3;        // tile quarter (32)
    const int cb = blockIdx.x >> 3;   // co block (128)
    const int nb = blockIdx.x & 7;    // tile block (128)
    const int u  = blockIdx.y;
    const int b  = blockIdx.z;
    const int tile0 = nb * 128;

    unsigned sm_u = (unsigned)__cvta_generic_to_shared(smem);

    const uint4* dsrc = (const uint4*)g_d + (size_t)(b*16+u)*65536 + (tile0 >> 2);
    const uint4* wsrc = (const uint4*)g_wg + (size_t)u*32768 + (size_t)cb*8192;

    float acc[4][4][4];
    #pragma unroll
    for (int i=0;i<4;i++)
      #pragma unroll
      for (int j=0;j<4;j++)
        #pragma unroll
        for (int k=0;k<4;k++) acc[i][j][k]=0.f;

    auto load = [&](int kc){
        unsigned base = sm_u + (unsigned)((kc % 3) * STAGE_B);
        #pragma unroll
        for (int k = 0; k < 2; k++){
            int idx = tid + k*256;
            int cp = idx >> 5, q = idx & 31;
            asm volatile("cp.async.cg.shared.global [%0], [%1], 16;"
                         :: "r"(base + (unsigned)((cp*DSTR + q*4)*4)),
                            "l"(dsrc + (size_t)(kc*16 + cp)*256 + q));
        }
        #pragma unroll
        for (int k = 0; k < 2; k++){
            int idx = tid + k*256;
            asm volatile("cp.async.cg.shared.global [%0], [%1], 16;"
                         :: "r"(base + (unsigned)(DCH_B + idx*16)), "l"(wsrc + kc*512 + idx));
        }
    };

    load(0);
    asm volatile("cp.async.commit_group;");
    load(1);
    asm volatile("cp.async.commit_group;");

    for (int kc = 0; kc < 16; kc++){
        asm volatile("cp.async.wait_group 1;");
        __syncthreads();

        const uint32_t* xb = (const uint32_t*)(smem + (kc % 3)*STAGE_B) + wn*32 + (lane >> 2);
        const float4*  w4 = (const float4*)(smem + (kc % 3)*STAGE_B + DCH_B);

        #pragma unroll
        for (int ks = 0; ks < 2; ks++){
            const uint32_t* xp = xb + (ks*8 + (lane & 3)) * DSTR;
            uint32_t bf[4][2];
            #pragma unroll
            for (int nt = 0; nt < 4; nt++){
                bf[nt][0] = xp[nt*8];
                bf[nt][1] = xp[nt*8 + 4*DSTR];
            }
            #pragma unroll
            for (int mt = 0; mt < 4; mt++){
                float4 a = w4[(ks*8 + wm*4 + mt)*32 + lane];
                uint32_t a0=__float_as_uint(a.x), a1=__float_as_uint(a.y),
                         a2=__float_as_uint(a.z), a3=__float_as_uint(a.w);
                #pragma unroll
                for (int nt = 0; nt < 4; nt++)
                    mma_f16(acc[mt][nt], a0,a1,a2,a3, bf[nt][0], bf[nt][1]);
            }
        }
        __syncthreads();
        if (kc + 2 < 16) load(kc + 2);
        asm volatile("cp.async.commit_group;");
    }

    // epilogue: write M as fp16
    #pragma unroll
    for (int mt = 0; mt < 4; mt++){
        int co = cb*128 + wm*64 + mt*16 + (lane >> 2);
        size_t rb = ((size_t)(b*16+u)*512 + co)*1024;
        #pragma unroll
        for (int nt = 0; nt < 4; nt++){
            int tile = tile0 + wn*32 + nt*8 + (lane & 3)*2;
            __half2 v0 = __floats2half2_rn(acc[mt][nt][0], acc[mt][nt][1]);
            __half2 v1 = __floats2half2_rn(acc[mt][nt][2], acc[mt][nt][3]);
            *(__half2*)(g_m + rb + tile)          = v0;
            *(__half2*)(g_m + rb + 8*1024 + tile) = v1;
        }
    }
}

// ---------------- inverse transform: out = A^T M A * dscale (tile-pair vectorized) ----------------
__global__ void inv_kernel(float* __restrict__ out){
    int co = blockIdx.x, b = blockIdx.y, tid = threadIdx.x;
    float ds = g_dscale[b*512 + co];
    const __half2* mp = (const __half2*)(g_m + ((size_t)(b*16)*512 + co)*1024);  // u-stride 262144 half2
    float* op = out + ((size_t)(b*512 + co))*NPIX;
    #pragma unroll
    for (int tt = 0; tt < 2; tt++){
        int pr = tid + tt*256;                 // tile-pair index: tiles (2pr, 2pr+1)
        int i = pr >> 4, jc = (pr & 15) * 4;   // row i, output col base 4*(pr&15)
        float2 m[16];
        #pragma unroll
        for (int u = 0; u < 16; u++)
            m[u] = __half22float2(mp[(size_t)u*262144 + pr]);
        float2 p0[4], p1[4];
        #pragma unroll
        for (int c = 0; c < 4; c++){
            p0[c] = make_float2(m[c].x + m[4+c].x + m[8+c].x,
                                m[c].y + m[4+c].y + m[8+c].y);
            p1[c] = make_float2(m[4+c].x - m[8+c].x - m[12+c].x,
                                m[4+c].y - m[8+c].y - m[12+c].y);
        }
        float4 r0 = make_float4((p0[0].x+p0[1].x+p0[2].x)*ds, (p0[1].x-p0[2].x-p0[3].x)*ds,
                                (p0[0].y+p0[1].y+p0[2].y)*ds, (p0[1].y-p0[2].y-p0[3].y)*ds);
        float4 r1 = make_float4((p1[0].x+p1[1].x+p1[2].x)*ds, (p1[1].x-p1[2].x-p1[3].x)*ds,
                                (p1[0].y+p1[1].y+p1[2].y)*ds, (p1[1].y-p1[2].y-p1[3].y)*ds);
        *(float4*)(op + (2*i)*64   + jc) = r0;
        *(float4*)(op + (2*i+1)*64 + jc) = r1;
    }
}

// ---------------- launcher ----------------
extern "C" void kernel_launch(void* const* d_in, const int* in_sizes, int n_in,
                              void* d_out, int out_size){
    const float* input      = (const float*)d_in[0];
    const float* style      = (const float*)d_in[1];
    const float* weight     = (const float*)d_in[2];
    const float* mod_weight = (const float*)d_in[3];
    const float* mod_bias   = (const float*)d_in[4];
    float* out = (float*)d_out;

    cudaFuncSetAttribute(gemm_kernel, cudaFuncAttributeMaxDynamicSharedMemorySize, GEMM_SMEM);

    mod_kernel    <<<16, 512>>>(style, mod_weight, mod_bias);
    wtrans_kernel <<<1024, 256>>>(weight);
    demod_kernel  <<<16, 512>>>();
    dtrans_kernel <<<dim3(256,16), 256>>>(input);
    gemm_kernel   <<<dim3(32,16,16), 256, GEMM_SMEM>>>();
    inv_kernel    <<<dim3(512,16), 256>>>(out);
}

// round 10
// speedup vs baseline: 2.3043x; 1.0262x over previous
#include <cuda_runtime.h>
#include <cuda_fp16.h>
#include <cstdint>
#include <cstddef>

#define BATCH 16
#define CIN   512
#define COUT  512
#define NPIX  4096
#define MOD_SCALE  0.044194173824159216f
#define CONV_SCALE 0.014731391274719739f

// Winograd F(2x2,3x3): 1024 tiles/image, 16 transform points (u)
// GEMM per (u,b): M_u[512co,1024t] = W_u[512co,512ci] * D_u[512ci,1024t]
// CTA tile: 128co x 128t, K-chunk 32ci, 3-stage cp.async, 2 CTAs/SM

#define DSTR   136                          // 128 tiles + 8 pad words (8 mod 32 -> conflict-free)
#define DCH_B  (16*DSTR*4)                  // 8704 B per D stage
#define STAGE_B (DCH_B + 8192)              // 16896 B (D + W)
#define GEMM_SMEM (3*STAGE_B)               // 50688 B

// ---------------- device scratch ----------------
__device__ float g_s[BATCH*CIN];
__device__ float g_wsq[COUT*CIN];
__device__ float g_dscale[BATCH*COUT];
__device__ __align__(128) __half   g_wg[16*4*16*4096];                 // 8 MB transformed W, frag-packed
__device__ __align__(128) uint32_t g_d[(size_t)16*16*256*1024];        // 268 MB transformed input (f16x2 ci-pairs)
__device__ __align__(128) __half   g_m[(size_t)16*16*512*1024];        // 268 MB GEMM output M

// ---------------- s[b][ci] = style @ (mod_weight*MOD_SCALE)^T + bias ----------------
__global__ void mod_kernel(const float* __restrict__ style,
                           const float* __restrict__ mod_weight,
                           const float* __restrict__ mod_bias){
    __shared__ float st[512];
    int b = blockIdx.x, t = threadIdx.x;
    st[t] = style[b*512 + t];
    __syncthreads();
    const float* wr = mod_weight + t*512;
    float acc = 0.f;
    #pragma unroll 8
    for (int j = 0; j < 512; j++) acc = fmaf(st[j], wr[j], acc);
    g_s[b*512 + t] = acc * MOD_SCALE + mod_bias[t];
}

// ---------------- dscale[b][o] = CONV_SCALE * rsqrt(CONV_SCALE^2 * sum s^2*wsq + 1e-8) ----------------
__global__ void demod_kernel(){
    __shared__ float s2[512];
    int b = blockIdx.x, t = threadIdx.x;
    float sv = g_s[b*512 + t];
    s2[t] = sv*sv;
    __syncthreads();
    const float* wr = g_wsq + t*512;
    float acc = 0.f;
    #pragma unroll 8
    for (int j = 0; j < 512; j++) acc = fmaf(s2[j], wr[j], acc);
    float v = CONV_SCALE*CONV_SCALE*acc + 1e-8f;
    g_dscale[b*512 + t] = CONV_SCALE / sqrtf(v);
}

// ---------------- weight transform U = G g G^T (frag-packed fp16) + fused wsq ----------------
// g_wg layout: [u][cb(4)][kc(16)] tile of 4096 halves: [ks(2)][mt(8)][lane(32)][r(4) x f16x2]
__global__ void wtrans_kernel(const float* __restrict__ w){
    int i = blockIdx.x*256 + threadIdx.x;          // 262144 = co*512+ci
    int co = i >> 9, ci = i & 511;
    const float* p = w + (size_t)i*9;
    float g[3][3];
    float sq = 0.f;
    #pragma unroll
    for (int r = 0; r < 3; r++)
        #pragma unroll
        for (int c = 0; c < 3; c++){ g[r][c] = p[r*3+c]; sq = fmaf(g[r][c], g[r][c], sq); }
    g_wsq[i] = sq;
    float t[4][3];
    #pragma unroll
    for (int c = 0; c < 3; c++){
        t[0][c] = g[0][c];
        t[1][c] = 0.5f*(g[0][c]+g[1][c]+g[2][c]);
        t[2][c] = 0.5f*(g[0][c]-g[1][c]+g[2][c]);
        t[3][c] = g[2][c];
    }
    float U[16];
    #pragma unroll
    for (int r = 0; r < 4; r++){
        U[r*4+0] = t[r][0];
        U[r*4+1] = 0.5f*(t[r][0]+t[r][1]+t[r][2]);
        U[r*4+2] = 0.5f*(t[r][0]-t[r][1]+t[r][2]);
        U[r*4+3] = t[r][2];
    }
    int kc = ci>>5, c5 = ci&31, ks = c5>>4, cc = c5&15;
    int lane = (co&7)*4 + ((cc>>1)&3);
    int r    = ((co>>3)&1) + ((cc>>3)&1)*2;
    int mt   = (co>>4)&7, cb = co>>7;
    size_t boff = ((size_t)(cb*16 + kc))*4096 + (size_t)(((ks*8+mt)*32+lane)<<3) + r*2 + (cc&1);
    #pragma unroll
    for (int u = 0; u < 16; u++)
        g_wg[boff + (size_t)u*262144] = __float2half_rn(U[u]);
}

// ---------------- input transform: D = B^T (s*x) B, fused s-scale, uint2 stores ----------------
// g_d word layout: [b][u][cipair(256)][tile(1024)], word = f16x2 (ci even, ci odd)
__global__ void dtrans_kernel(const float* __restrict__ x){
    __shared__ float2 spad[66*66];
    int cp = blockIdx.x, b = blockIdx.y, tid = threadIdx.x;
    const float* x0 = x + ((size_t)(b*512 + cp*2))*NPIX;
    const float* x1 = x0 + NPIX;
    float s0 = g_s[b*512 + cp*2];
    float s1 = g_s[b*512 + cp*2 + 1];
    for (int idx = tid; idx < 66*66; idx += 256){
        int r = idx / 66, c = idx - r*66;
        int ir = r - 1, ic = c - 1;
        float2 v = make_float2(0.f, 0.f);
        if ((unsigned)ir < 64u && (unsigned)ic < 64u){
            v.x = x0[ir*64 + ic] * s0;
            v.y = x1[ir*64 + ic] * s1;
        }
        spad[idx] = v;
    }
    __syncthreads();

    auto tilepack = [&](int i, int j, uint32_t* outp){
        float2 d[4][4];
        #pragma unroll
        for (int rr = 0; rr < 4; rr++)
            #pragma unroll
            for (int cc = 0; cc < 4; cc++) d[rr][cc] = spad[(2*i+rr)*66 + 2*j+cc];
        float tx[4][4], ty[4][4];
        #pragma unroll
        for (int c = 0; c < 4; c++){
            tx[0][c] = d[0][c].x - d[2][c].x;  ty[0][c] = d[0][c].y - d[2][c].y;
            tx[1][c] = d[1][c].x + d[2][c].x;  ty[1][c] = d[1][c].y + d[2][c].y;
            tx[2][c] = d[2][c].x - d[1][c].x;  ty[2][c] = d[2][c].y - d[1][c].y;
            tx[3][c] = d[1][c].x - d[3][c].x;  ty[3][c] = d[1][c].y - d[3][c].y;
        }
        #pragma unroll
        for (int r = 0; r < 4; r++){
            __half2 h0 = __floats2half2_rn(tx[r][0] - tx[r][2], ty[r][0] - ty[r][2]);
            __half2 h1 = __floats2half2_rn(tx[r][1] + tx[r][2], ty[r][1] + ty[r][2]);
            __half2 h2 = __floats2half2_rn(tx[r][2] - tx[r][1], ty[r][2] - ty[r][1]);
            __half2 h3 = __floats2half2_rn(tx[r][1] - tx[r][3], ty[r][1] - ty[r][3]);
            outp[r*4+0] = *(uint32_t*)&h0;
            outp[r*4+1] = *(uint32_t*)&h1;
            outp[r*4+2] = *(uint32_t*)&h2;
            outp[r*4+3] = *(uint32_t*)&h3;
        }
    };

    #pragma unroll
    for (int pp = 0; pp < 2; pp++){
        int q = pp*256 + tid;                 // tile-pair index: tiles 2q, 2q+1
        int i = q >> 4, j0 = (q & 15)*2;
        uint32_t ua[16], ub[16];
        tilepack(i, j0,   ua);
        tilepack(i, j0+1, ub);
        size_t gbase = ((size_t)(b*16)*256 + cp)*1024 + 2*q;
        #pragma unroll
        for (int u = 0; u < 16; u++)
            *(uint2*)&g_d[gbase + (size_t)u*262144] = make_uint2(ua[u], ub[u]);
    }
}

// ---------------- GEMM: fp16 m16n8k16, fp32 accum, 128co x 128t, occ 2, 3-stage ----------------
__device__ __forceinline__ void mma_f16(float* c, uint32_t a0,uint32_t a1,uint32_t a2,uint32_t a3,
                                        uint32_t b0,uint32_t b1){
    asm volatile("mma.sync.aligned.m16n8k16.row.col.f32.f16.f16.f32 "
        "{%0,%1,%2,%3}, {%4,%5,%6,%7}, {%8,%9}, {%0,%1,%2,%3};"
        : "+f"(c[0]), "+f"(c[1]), "+f"(c[2]), "+f"(c[3])
        : "r"(a0), "r"(a1), "r"(a2), "r"(a3), "r"(b0), "r"(b1));
}

__global__ __launch_bounds__(256,2) void gemm_kernel(){
    extern __shared__ char smem[];
    const int tid  = threadIdx.x;
    const int lane = tid & 31;
    const int warp = tid >> 5;
    const int wm   = warp >> 2;       // co half (64)
    const int wn   = warp & 3;        // tile quarter (32)
    const int cb = blockIdx.x >> 3;   // co block (128)
    const int nb = blockIdx.x & 7;    // tile block (128)
    const int u  = blockIdx.y;
    const int b  = blockIdx.z;
    const int tile0 = nb * 128;

    unsigned sm_u = (unsigned)__cvta_generic_to_shared(smem);

    const uint4* dsrc = (const uint4*)g_d + (size_t)(b*16+u)*65536 + (tile0 >> 2);
    const uint4* wsrc = (const uint4*)g_wg + (size_t)u*32768 + (size_t)cb*8192;

    float acc[4][4][4];
    #pragma unroll
    for (int i=0;i<4;i++)
      #pragma unroll
      for (int j=0;j<4;j++)
        #pragma unroll
        for (int k=0;k<4;k++) acc[i][j][k]=0.f;

    auto load = [&](int kc){
        unsigned base = sm_u + (unsigned)((kc % 3) * STAGE_B);
        #pragma unroll
        for (int k = 0; k < 2; k++){
            int idx = tid + k*256;
            int cp = idx >> 5, q = idx & 31;
            asm volatile("cp.async.cg.shared.global [%0], [%1], 16;"
                         :: "r"(base + (unsigned)((cp*DSTR + q*4)*4)),
                            "l"(dsrc + (size_t)(kc*16 + cp)*256 + q));
        }
        #pragma unroll
        for (int k = 0; k < 2; k++){
            int idx = tid + k*256;
            asm volatile("cp.async.cg.shared.global [%0], [%1], 16;"
                         :: "r"(base + (unsigned)(DCH_B + idx*16)), "l"(wsrc + kc*512 + idx));
        }
    };

    load(0);
    asm volatile("cp.async.commit_group;");
    load(1);
    asm volatile("cp.async.commit_group;");

    for (int kc = 0; kc < 16; kc++){
        asm volatile("cp.async.wait_group 1;");
        __syncthreads();

        const uint32_t* xb = (const uint32_t*)(smem + (kc % 3)*STAGE_B) + wn*32 + (lane >> 2);
        const float4*  w4 = (const float4*)(smem + (kc % 3)*STAGE_B + DCH_B);

        #pragma unroll
        for (int ks = 0; ks < 2; ks++){
            const uint32_t* xp = xb + (ks*8 + (lane & 3)) * DSTR;
            uint32_t bf[4][2];
            #pragma unroll
            for (int nt = 0; nt < 4; nt++){
                bf[nt][0] = xp[nt*8];
                bf[nt][1] = xp[nt*8 + 4*DSTR];
            }
            #pragma unroll
            for (int mt = 0; mt < 4; mt++){
                float4 a = w4[(ks*8 + wm*4 + mt)*32 + lane];
                uint32_t a0=__float_as_uint(a.x), a1=__float_as_uint(a.y),
                         a2=__float_as_uint(a.z), a3=__float_as_uint(a.w);
                #pragma unroll
                for (int nt = 0; nt < 4; nt++)
                    mma_f16(acc[mt][nt], a0,a1,a2,a3, bf[nt][0], bf[nt][1]);
            }
        }
        // NOTE: no barrier needed before prefetch — stage (kc+2)%3 was last read in
        // iteration kc-1, already fenced by this iteration's top-of-loop barrier.
        if (kc + 2 < 16) load(kc + 2);
        asm volatile("cp.async.commit_group;");
    }

    // epilogue: write M as fp16
    #pragma unroll
    for (int mt = 0; mt < 4; mt++){
        int co = cb*128 + wm*64 + mt*16 + (lane >> 2);
        size_t rb = ((size_t)(b*16+u)*512 + co)*1024;
        #pragma unroll
        for (int nt = 0; nt < 4; nt++){
            int tile = tile0 + wn*32 + nt*8 + (lane & 3)*2;
            __half2 v0 = __floats2half2_rn(acc[mt][nt][0], acc[mt][nt][1]);
            __half2 v1 = __floats2half2_rn(acc[mt][nt][2], acc[mt][nt][3]);
            *(__half2*)(g_m + rb + tile)          = v0;
            *(__half2*)(g_m + rb + 8*1024 + tile) = v1;
        }
    }
}

// ---------------- inverse transform: out = A^T M A * dscale (4 tiles/thread, uint2 loads) ----------------
__global__ void inv_kernel(float* __restrict__ out){
    int co = blockIdx.x, b = blockIdx.y, tid = threadIdx.x;
    float ds = g_dscale[b*512 + co];
    const uint2* mp = (const uint2*)(g_m + ((size_t)(b*16)*512 + co)*1024);  // u-stride 131072 uint2
    float* op = out + ((size_t)(b*512 + co))*NPIX;

    int p = tid;                           // 4-tile group: tiles 4p..4p+3
    int i = p >> 3, j0 = (p & 7) * 8;      // output row pair i, col base

    float2 ma[16], mb[16];                 // ma: tiles 4p,4p+1  mb: tiles 4p+2,4p+3
    #pragma unroll
    for (int u = 0; u < 16; u++){
        uint2 v = mp[(size_t)u*131072 + p];
        ma[u] = __half22float2(*(__half2*)&v.x);
        mb[u] = __half22float2(*(__half2*)&v.y);
    }

    float2 p0a[4], p1a[4], p0b[4], p1b[4];
    #pragma unroll
    for (int c = 0; c < 4; c++){
        p0a[c] = make_float2(ma[c].x + ma[4+c].x + ma[8+c].x,
                             ma[c].y + ma[4+c].y + ma[8+c].y);
        p1a[c] = make_float2(ma[4+c].x - ma[8+c].x - ma[12+c].x,
                             ma[4+c].y - ma[8+c].y - ma[12+c].y);
        p0b[c] = make_float2(mb[c].x + mb[4+c].x + mb[8+c].x,
                             mb[c].y + mb[4+c].y + mb[8+c].y);
        p1b[c] = make_float2(mb[4+c].x - mb[8+c].x - mb[12+c].x,
                             mb[4+c].y - mb[8+c].y - mb[12+c].y);
    }
    float4 r0a = make_float4((p0a[0].x+p0a[1].x+p0a[2].x)*ds, (p0a[1].x-p0a[2].x-p0a[3].x)*ds,
                             (p0a[0].y+p0a[1].y+p0a[2].y)*ds, (p0a[1].y-p0a[2].y-p0a[3].y)*ds);
    float4 r1a = make_float4((p1a[0].x+p1a[1].x+p1a[2].x)*ds, (p1a[1].x-p1a[2].x-p1a[3].x)*ds,
                             (p1a[0].y+p1a[1].y+p1a[2].y)*ds, (p1a[1].y-p1a[2].y-p1a[3].y)*ds);
    float4 r0b = make_float4((p0b[0].x+p0b[1].x+p0b[2].x)*ds, (p0b[1].x-p0b[2].x-p0b[3].x)*ds,
                             (p0b[0].y+p0b[1].y+p0b[2].y)*ds, (p0b[1].y-p0b[2].y-p0b[3].y)*ds);
    float4 r1b = make_float4((p1b[0].x+p1b[1].x+p1b[2].x)*ds, (p1b[1].x-p1b[2].x-p1b[3].x)*ds,
                             (p1b[0].y+p1b[1].y+p1b[2].y)*ds, (p1b[1].y-p1b[2].y-p1b[3].y)*ds);

    *(float4*)(op + (2*i)*64   + j0)     = r0a;
    *(float4*)(op + (2*i)*64   + j0 + 4) = r0b;
    *(float4*)(op + (2*i+1)*64 + j0)     = r1a;
    *(float4*)(op + (2*i+1)*64 + j0 + 4) = r1b;
}

// ---------------- launcher ----------------
extern "C" void kernel_launch(void* const* d_in, const int* in_sizes, int n_in,
                              void* d_out, int out_size){
    const float* input      = (const float*)d_in[0];
    const float* style      = (const float*)d_in[1];
    const float* weight     = (const float*)d_in[2];
    const float* mod_weight = (const float*)d_in[3];
    const float* mod_bias   = (const float*)d_in[4];
    float* out = (float*)d_out;

    cudaFuncSetAttribute(gemm_kernel, cudaFuncAttributeMaxDynamicSharedMemorySize, GEMM_SMEM);

    mod_kernel    <<<16, 512>>>(style, mod_weight, mod_bias);
    wtrans_kernel <<<1024, 256>>>(weight);
    demod_kernel  <<<16, 512>>>();
    dtrans_kernel <<<dim3(256,16), 256>>>(input);
    gemm_kernel   <<<dim3(32,16,16), 256, GEMM_SMEM>>>();
    inv_kernel    <<<dim3(512,16), 256>>>(out);
}

// round 12
// speedup vs baseline: 2.5040x; 1.0867x over previous
#include <cuda_runtime.h>
#include <cuda_fp16.h>
#include <cstdint>
#include <cstddef>

#define BATCH 16
#define CIN   512
#define COUT  512
#define NPIX  4096
#define MOD_SCALE  0.044194173824159216f
#define CONV_SCALE 0.014731391274719739f

// Winograd F(2x2,3x3): 1024 tiles/image, 16 transform points (u)
// GEMM per (u,b): M_u[512co,1024t] = W_u[512co,512ci] * D_u[512ci,1024t]
// CTA tile: 128co x 128t, K-chunk 64ci, 3-stage cp.async, 2 CTAs/SM

#define DSTR   136                          // 128 tiles + 8 pad words (8 mod 32 -> conflict-free)
#define DCH_B  (32*DSTR*4)                  // 17408 B per D stage (32 cipairs)
#define WCH_B  16384                        // 64ci x 128co fp16
#define STAGE_B (DCH_B + WCH_B)             // 33792 B
#define GEMM_SMEM (3*STAGE_B)               // 101376 B

#define PSTR 72                             // dtrans smem plane stride (floats)

// ---------------- device scratch ----------------
__device__ float g_s[BATCH*CIN];
__device__ float g_wsq[COUT*CIN];
__device__ float g_dscale[BATCH*COUT];
__device__ __align__(128) __half   g_wg[16*4*16*4096];                 // 8 MB transformed W, frag-packed
__device__ __align__(128) uint32_t g_d[(size_t)16*16*256*1024];        // 268 MB transformed input (f16x2 ci-pairs)
__device__ __align__(128) __half   g_m[(size_t)16*16*512*1024];        // 268 MB GEMM output M

// ---------------- s[b][ci] = style @ (mod_weight*MOD_SCALE)^T + bias ----------------
__global__ void mod_kernel(const float* __restrict__ style,
                           const float* __restrict__ mod_weight,
                           const float* __restrict__ mod_bias){
    __shared__ float st[512];
    int b = blockIdx.x, t = threadIdx.x;
    st[t] = style[b*512 + t];
    __syncthreads();
    const float* wr = mod_weight + t*512;
    float acc = 0.f;
    #pragma unroll 8
    for (int j = 0; j < 512; j++) acc = fmaf(st[j], wr[j], acc);
    g_s[b*512 + t] = acc * MOD_SCALE + mod_bias[t];
}

// ---------------- dscale[b][o] = CONV_SCALE * rsqrt(CONV_SCALE^2 * sum s^2*wsq + 1e-8) ----------------
__global__ void demod_kernel(){
    __shared__ float s2[512];
    int b = blockIdx.x, t = threadIdx.x;
    float sv = g_s[b*512 + t];
    s2[t] = sv*sv;
    __syncthreads();
    const float* wr = g_wsq + t*512;
    float acc = 0.f;
    #pragma unroll 8
    for (int j = 0; j < 512; j++) acc = fmaf(s2[j], wr[j], acc);
    float v = CONV_SCALE*CONV_SCALE*acc + 1e-8f;
    g_dscale[b*512 + t] = CONV_SCALE / sqrtf(v);
}

// ---------------- weight transform U = G g G^T (frag-packed fp16) + fused wsq ----------------
// g_wg layout: [u][cb(4)][kc(16)] tile of 4096 halves: [ks(2)][mt(8)][lane(32)][r(4) x f16x2]
__global__ void wtrans_kernel(const float* __restrict__ w){
    int i = blockIdx.x*256 + threadIdx.x;          // 262144 = co*512+ci
    int co = i >> 9, ci = i & 511;
    const float* p = w + (size_t)i*9;
    float g[3][3];
    float sq = 0.f;
    #pragma unroll
    for (int r = 0; r < 3; r++)
        #pragma unroll
        for (int c = 0; c < 3; c++){ g[r][c] = p[r*3+c]; sq = fmaf(g[r][c], g[r][c], sq); }
    g_wsq[i] = sq;
    float t[4][3];
    #pragma unroll
    for (int c = 0; c < 3; c++){
        t[0][c] = g[0][c];
        t[1][c] = 0.5f*(g[0][c]+g[1][c]+g[2][c]);
        t[2][c] = 0.5f*(g[0][c]-g[1][c]+g[2][c]);
        t[3][c] = g[2][c];
    }
    float U[16];
    #pragma unroll
    for (int r = 0; r < 4; r++){
        U[r*4+0] = t[r][0];
        U[r*4+1] = 0.5f*(t[r][0]+t[r][1]+t[r][2]);
        U[r*4+2] = 0.5f*(t[r][0]-t[r][1]+t[r][2]);
        U[r*4+3] = t[r][2];
    }
    int kc = ci>>5, c5 = ci&31, ks = c5>>4, cc = c5&15;
    int lane = (co&7)*4 + ((cc>>1)&3);
    int r    = ((co>>3)&1) + ((cc>>3)&1)*2;
    int mt   = (co>>4)&7, cb = co>>7;
    size_t boff = ((size_t)(cb*16 + kc))*4096 + (size_t)(((ks*8+mt)*32+lane)<<3) + r*2 + (cc&1);
    #pragma unroll
    for (int u = 0; u < 16; u++)
        g_wg[boff + (size_t)u*262144] = __float2half_rn(U[u]);
}

// ---------------- input transform: D = B^T x B * s, cp.async padded planes ----------------
// g_d word layout: [b][u][cipair(256)][tile(1024)], word = f16x2 (ci even, ci odd)
__global__ void dtrans_kernel(const float* __restrict__ x){
    __shared__ float sp[2*66*PSTR];        // two padded planes, 38016 B
    int cp = blockIdx.x, b = blockIdx.y, tid = threadIdx.x;
    const float* x0 = x + ((size_t)(b*512 + cp*2))*NPIX;
    const float* x1 = x0 + NPIX;
    float s0 = g_s[b*512 + cp*2];
    float s1 = g_s[b*512 + cp*2 + 1];

    // zero-fill both planes
    float4 z = make_float4(0.f,0.f,0.f,0.f);
    for (int i = tid; i < 2*66*PSTR/4; i += 256) ((float4*)sp)[i] = z;
    __syncthreads();

    // bulk interior load: image row ir -> spad row ir+1, image col c -> spad col c+4
    // 2 planes * 64 rows * 16 chunks of 16 BYTES (4 floats) = 2048 cp.async ops
    unsigned spu = (unsigned)__cvta_generic_to_shared(sp);
    #pragma unroll
    for (int k = 0; k < 8; k++){
        int t = tid + k*256;               // 0..2047
        int p  = t >> 10;
        int rm = t & 1023;
        int ir = rm >> 4, ch = rm & 15;
        unsigned dst = spu + (unsigned)((p*66*PSTR + (ir+1)*PSTR + 4 + ch*4)*4);
        const float* src = (p ? x1 : x0) + ir*64 + ch*4;
        asm volatile("cp.async.cg.shared.global [%0], [%1], 16;" :: "r"(dst), "l"(src));
    }
    asm volatile("cp.async.commit_group;");
    asm volatile("cp.async.wait_group 0;");
    __syncthreads();

    const float* sp0 = sp;
    const float* sp1 = sp + 66*PSTR;

    auto tilepack = [&](int i, int j, uint32_t* outp){
        float dx[4][4], dy[4][4];
        int base = (2*i)*PSTR + 2*j + 3;   // spad row 2i (image row 2i-1), col 2j+3 (image col 2j-1)
        #pragma unroll
        for (int rr = 0; rr < 4; rr++)
            #pragma unroll
            for (int cc = 0; cc < 4; cc++){
                dx[rr][cc] = sp0[base + rr*PSTR + cc] * s0;
                dy[rr][cc] = sp1[base + rr*PSTR + cc] * s1;
            }
        float tx[4][4], ty[4][4];
        #pragma unroll
        for (int c = 0; c < 4; c++){
            tx[0][c] = dx[0][c] - dx[2][c];  ty[0][c] = dy[0][c] - dy[2][c];
            tx[1][c] = dx[1][c] + dx[2][c];  ty[1][c] = dy[1][c] + dy[2][c];
            tx[2][c] = dx[2][c] - dx[1][c];  ty[2][c] = dy[2][c] - dy[1][c];
            tx[3][c] = dx[1][c] - dx[3][c];  ty[3][c] = dy[1][c] - dy[3][c];
        }
        #pragma unroll
        for (int r = 0; r < 4; r++){
            __half2 h0 = __floats2half2_rn(tx[r][0] - tx[r][2], ty[r][0] - ty[r][2]);
            __half2 h1 = __floats2half2_rn(tx[r][1] + tx[r][2], ty[r][1] + ty[r][2]);
            __half2 h2 = __floats2half2_rn(tx[r][2] - tx[r][1], ty[r][2] - ty[r][1]);
            __half2 h3 = __floats2half2_rn(tx[r][1] - tx[r][3], ty[r][1] - ty[r][3]);
            outp[r*4+0] = *(uint32_t*)&h0;
            outp[r*4+1] = *(uint32_t*)&h1;
            outp[r*4+2] = *(uint32_t*)&h2;
            outp[r*4+3] = *(uint32_t*)&h3;
        }
    };

    #pragma unroll
    for (int pp = 0; pp < 2; pp++){
        int q = pp*256 + tid;              // tile-pair index: tiles 2q, 2q+1
        int i = q >> 4, j0 = (q & 15)*2;
        uint32_t ua[16], ub[16];
        tilepack(i, j0,   ua);
        tilepack(i, j0+1, ub);
        size_t gbase = ((size_t)(b*16)*256 + cp)*1024 + 2*q;
        #pragma unroll
        for (int u = 0; u < 16; u++)
            *(uint2*)&g_d[gbase + (size_t)u*262144] = make_uint2(ua[u], ub[u]);
    }
}

// ---------------- GEMM: fp16 m16n8k16, fp32 accum, 128co x 128t, K-chunk 64, occ 2, 3-stage ----------------
__device__ __forceinline__ void mma_f16(float* c, uint32_t a0,uint32_t a1,uint32_t a2,uint32_t a3,
                                        uint32_t b0,uint32_t b1){
    asm volatile("mma.sync.aligned.m16n8k16.row.col.f32.f16.f16.f32 "
        "{%0,%1,%2,%3}, {%4,%5,%6,%7}, {%8,%9}, {%0,%1,%2,%3};"
        : "+f"(c[0]), "+f"(c[1]), "+f"(c[2]), "+f"(c[3])
        : "r"(a0), "r"(a1), "r"(a2), "r"(a3), "r"(b0), "r"(b1));
}

__global__ __launch_bounds__(256,2) void gemm_kernel(){
    extern __shared__ char smem[];
    const int tid  = threadIdx.x;
    const int lane = tid & 31;
    const int warp = tid >> 5;
    const int wm   = warp >> 2;       // co half (64)
    const int wn   = warp & 3;        // tile quarter (32)
    const int cb = blockIdx.x >> 3;   // co block (128)
    const int nb = blockIdx.x & 7;    // tile block (128)
    const int u  = blockIdx.y;
    const int b  = blockIdx.z;
    const int tile0 = nb * 128;

    unsigned sm_u = (unsigned)__cvta_generic_to_shared(smem);

    const uint4* dsrc = (const uint4*)g_d + (size_t)(b*16+u)*65536 + (tile0 >> 2);
    const uint4* wsrc = (const uint4*)g_wg + (size_t)u*32768 + (size_t)cb*8192;

    float acc[4][4][4];
    #pragma unroll
    for (int i=0;i<4;i++)
      #pragma unroll
      for (int j=0;j<4;j++)
        #pragma unroll
        for (int k=0;k<4;k++) acc[i][j][k]=0.f;

    auto load = [&](int kc){              // kc in 0..7, 64 ci per chunk
        unsigned base = sm_u + (unsigned)((kc % 3) * STAGE_B);
        #pragma unroll
        for (int k = 0; k < 4; k++){
            int idx = tid + k*256;        // 0..1023
            int cp = idx >> 5, q = idx & 31;
            asm volatile("cp.async.cg.shared.global [%0], [%1], 16;"
                         :: "r"(base + (unsigned)((cp*DSTR + q*4)*4)),
                            "l"(dsrc + (size_t)(kc*32 + cp)*256 + q));
        }
        #pragma unroll
        for (int k = 0; k < 4; k++){
            int idx = tid + k*256;        // 0..1023
            asm volatile("cp.async.cg.shared.global [%0], [%1], 16;"
                         :: "r"(base + (unsigned)(DCH_B + idx*16)), "l"(wsrc + kc*1024 + idx));
        }
    };

    load(0);
    asm volatile("cp.async.commit_group;");
    load(1);
    asm volatile("cp.async.commit_group;");

    for (int kc = 0; kc < 8; kc++){
        asm volatile("cp.async.wait_group 1;");
        __syncthreads();

        const uint32_t* xb = (const uint32_t*)(smem + (kc % 3)*STAGE_B) + wn*32 + (lane >> 2);
        const float4*  w4 = (const float4*)(smem + (kc % 3)*STAGE_B + DCH_B);

        #pragma unroll
        for (int ks = 0; ks < 4; ks++){   // 4 x k16 within 64-ci chunk
            const uint32_t* xp = xb + (ks*8 + (lane & 3)) * DSTR;
            uint32_t bf[4][2];
            #pragma unroll
            for (int nt = 0; nt < 4; nt++){
                bf[nt][0] = xp[nt*8];
                bf[nt][1] = xp[nt*8 + 4*DSTR];
            }
            #pragma unroll
            for (int mt = 0; mt < 4; mt++){
                float4 a = w4[(ks>>1)*512 + (((ks&1)*8 + wm*4 + mt)*32 + lane)];
                uint32_t a0=__float_as_uint(a.x), a1=__float_as_uint(a.y),
                         a2=__float_as_uint(a.z), a3=__float_as_uint(a.w);
                #pragma unroll
                for (int nt = 0; nt < 4; nt++)
                    mma_f16(acc[mt][nt], a0,a1,a2,a3, bf[nt][0], bf[nt][1]);
            }
        }
        // no barrier needed before prefetch: stage (kc+2)%3 was last read in iteration
        // kc-1, already fenced by this iteration's top-of-loop barrier.
        if (kc + 2 < 8) load(kc + 2);
        asm volatile("cp.async.commit_group;");
    }

    // epilogue: write M as fp16
    #pragma unroll
    for (int mt = 0; mt < 4; mt++){
        int co = cb*128 + wm*64 + mt*16 + (lane >> 2);
        size_t rb = ((size_t)(b*16+u)*512 + co)*1024;
        #pragma unroll
        for (int nt = 0; nt < 4; nt++){
            int tile = tile0 + wn*32 + nt*8 + (lane & 3)*2;
            __half2 v0 = __floats2half2_rn(acc[mt][nt][0], acc[mt][nt][1]);
            __half2 v1 = __floats2half2_rn(acc[mt][nt][2], acc[mt][nt][3]);
            *(__half2*)(g_m + rb + tile)          = v0;
            *(__half2*)(g_m + rb + 8*1024 + tile) = v1;
        }
    }
}

// ---------------- inverse transform: out = A^T M A * dscale (4 tiles/thread, uint2 loads) ----------------
__global__ void inv_kernel(float* __restrict__ out){
    int co = blockIdx.x, b = blockIdx.y, tid = threadIdx.x;
    float ds = g_dscale[b*512 + co];
    const uint2* mp = (const uint2*)(g_m + ((size_t)(b*16)*512 + co)*1024);  // u-stride 131072 uint2
    float* op = out + ((size_t)(b*512 + co))*NPIX;

    int p = tid;                           // 4-tile group: tiles 4p..4p+3
    int i = p >> 3, j0 = (p & 7) * 8;      // output row pair i, col base

    float2 ma[16], mb[16];                 // ma: tiles 4p,4p+1  mb: tiles 4p+2,4p+3
    #pragma unroll
    for (int u = 0; u < 16; u++){
        uint2 v = mp[(size_t)u*131072 + p];
        ma[u] = __half22float2(*(__half2*)&v.x);
        mb[u] = __half22float2(*(__half2*)&v.y);
    }

    float2 p0a[4], p1a[4], p0b[4], p1b[4];
    #pragma unroll
    for (int c = 0; c < 4; c++){
        p0a[c] = make_float2(ma[c].x + ma[4+c].x + ma[8+c].x,
                             ma[c].y + ma[4+c].y + ma[8+c].y);
        p1a[c] = make_float2(ma[4+c].x - ma[8+c].x - ma[12+c].x,
                             ma[4+c].y - ma[8+c].y - ma[12+c].y);
        p0b[c] = make_float2(mb[c].x + mb[4+c].x + mb[8+c].x,
                             mb[c].y + mb[4+c].y + mb[8+c].y);
        p1b[c] = make_float2(mb[4+c].x - mb[8+c].x - mb[12+c].x,
                             mb[4+c].y - mb[8+c].y - mb[12+c].y);
    }
    float4 r0a = make_float4((p0a[0].x+p0a[1].x+p0a[2].x)*ds, (p0a[1].x-p0a[2].x-p0a[3].x)*ds,
                             (p0a[0].y+p0a[1].y+p0a[2].y)*ds, (p0a[1].y-p0a[2].y-p0a[3].y)*ds);
    float4 r1a = make_float4((p1a[0].x+p1a[1].x+p1a[2].x)*ds, (p1a[1].x-p1a[2].x-p1a[3].x)*ds,
                             (p1a[0].y+p1a[1].y+p1a[2].y)*ds, (p1a[1].y-p1a[2].y-p1a[3].y)*ds);
    float4 r0b = make_float4((p0b[0].x+p0b[1].x+p0b[2].x)*ds, (p0b[1].x-p0b[2].x-p0b[3].x)*ds,
                             (p0b[0].y+p0b[1].y+p0b[2].y)*ds, (p0b[1].y-p0b[2].y-p0b[3].y)*ds);
    float4 r1b = make_float4((p1b[0].x+p1b[1].x+p1b[2].x)*ds, (p1b[1].x-p1b[2].x-p1b[3].x)*ds,
                             (p1b[0].y+p1b[1].y+p1b[2].y)*ds, (p1b[1].y-p1b[2].y-p1b[3].y)*ds);

    *(float4*)(op + (2*i)*64   + j0)     = r0a;
    *(float4*)(op + (2*i)*64   + j0 + 4) = r0b;
    *(float4*)(op + (2*i+1)*64 + j0)     = r1a;
    *(float4*)(op + (2*i+1)*64 + j0 + 4) = r1b;
}

// ---------------- launcher ----------------
extern "C" void kernel_launch(void* const* d_in, const int* in_sizes, int n_in,
                              void* d_out, int out_size){
    const float* input      = (const float*)d_in[0];
    const float* style      = (const float*)d_in[1];
    const float* weight     = (const float*)d_in[2];
    const float* mod_weight = (const float*)d_in[3];
    const float* mod_bias   = (const float*)d_in[4];
    float* out = (float*)d_out;

    cudaFuncSetAttribute(gemm_kernel, cudaFuncAttributeMaxDynamicSharedMemorySize, GEMM_SMEM);

    mod_kernel    <<<16, 512>>>(style, mod_weight, mod_bias);
    wtrans_kernel <<<1024, 256>>>(weight);
    demod_kernel  <<<16, 512>>>();
    dtrans_kernel <<<dim3(256,16), 256>>>(input);
    gemm_kernel   <<<dim3(32,16,16), 256, GEMM_SMEM>>>();
    inv_kernel    <<<dim3(512,16), 256>>>(out);
}

// round 13
// speedup vs baseline: 2.5405x; 1.0146x over previous
#include <cuda_runtime.h>
#include <cuda_fp16.h>
#include <cstdint>
#include <cstddef>

#define BATCH 16
#define CIN   512
#define COUT  512
#define NPIX  4096
#define MOD_SCALE  0.044194173824159216f
#define CONV_SCALE 0.014731391274719739f

// Winograd F(2x2,3x3): 1024 tiles/image, 16 transform points (u)
// GEMM per (u,b): M_u[512co,1024t] = W_u[512co,512ci] * D_u[512ci,1024t]
// Persistent CTAs: 304 resident, rolling 3-stage cp.async across tiles.

#define DSTR   136                          // 128 tiles + 8 pad words (8 mod 32 -> conflict-free)
#define DCH_B  (32*DSTR*4)                  // 17408 B per D stage (32 cipairs)
#define WCH_B  16384                        // 64ci x 128co fp16
#define STAGE_B (DCH_B + WCH_B)             // 33792 B
#define GEMM_SMEM (3*STAGE_B)               // 101376 B
#define GEMM_GRID 304

#define PSTR 72                             // dtrans smem plane stride (floats)

// ---------------- device scratch ----------------
__device__ float g_s[BATCH*CIN];
__device__ float g_wsq[COUT*CIN];
__device__ float g_dscale[BATCH*COUT];
__device__ __align__(128) __half   g_wg[16*4*16*4096];                 // 8 MB transformed W, frag-packed
__device__ __align__(128) uint32_t g_d[(size_t)16*16*256*1024];        // 268 MB transformed input (f16x2 ci-pairs)
__device__ __align__(128) __half   g_m[(size_t)16*16*512*1024];        // 268 MB GEMM output M

// ---------------- s[b][ci] = style @ (mod_weight*MOD_SCALE)^T + bias ----------------
__global__ void mod_kernel(const float* __restrict__ style,
                           const float* __restrict__ mod_weight,
                           const float* __restrict__ mod_bias){
    __shared__ float st[512];
    int b = blockIdx.x, t = threadIdx.x;
    st[t] = style[b*512 + t];
    __syncthreads();
    const float* wr = mod_weight + t*512;
    float acc = 0.f;
    #pragma unroll 8
    for (int j = 0; j < 512; j++) acc = fmaf(st[j], wr[j], acc);
    g_s[b*512 + t] = acc * MOD_SCALE + mod_bias[t];
}

// ---------------- dscale[b][o] = CONV_SCALE * rsqrt(CONV_SCALE^2 * sum s^2*wsq + 1e-8) ----------------
__global__ void demod_kernel(){
    __shared__ float s2[512];
    int b = blockIdx.x, t = threadIdx.x;
    float sv = g_s[b*512 + t];
    s2[t] = sv*sv;
    __syncthreads();
    const float* wr = g_wsq + t*512;
    float acc = 0.f;
    #pragma unroll 8
    for (int j = 0; j < 512; j++) acc = fmaf(s2[j], wr[j], acc);
    float v = CONV_SCALE*CONV_SCALE*acc + 1e-8f;
    g_dscale[b*512 + t] = CONV_SCALE / sqrtf(v);
}

// ---------------- weight transform U = G g G^T (frag-packed fp16) + fused wsq ----------------
// g_wg layout: [u][cb(4)][kc(16)] tile of 4096 halves: [ks(2)][mt(8)][lane(32)][r(4) x f16x2]
__global__ void wtrans_kernel(const float* __restrict__ w){
    int i = blockIdx.x*256 + threadIdx.x;          // 262144 = co*512+ci
    int co = i >> 9, ci = i & 511;
    const float* p = w + (size_t)i*9;
    float g[3][3];
    float sq = 0.f;
    #pragma unroll
    for (int r = 0; r < 3; r++)
        #pragma unroll
        for (int c = 0; c < 3; c++){ g[r][c] = p[r*3+c]; sq = fmaf(g[r][c], g[r][c], sq); }
    g_wsq[i] = sq;
    float t[4][3];
    #pragma unroll
    for (int c = 0; c < 3; c++){
        t[0][c] = g[0][c];
        t[1][c] = 0.5f*(g[0][c]+g[1][c]+g[2][c]);
        t[2][c] = 0.5f*(g[0][c]-g[1][c]+g[2][c]);
        t[3][c] = g[2][c];
    }
    float U[16];
    #pragma unroll
    for (int r = 0; r < 4; r++){
        U[r*4+0] = t[r][0];
        U[r*4+1] = 0.5f*(t[r][0]+t[r][1]+t[r][2]);
        U[r*4+2] = 0.5f*(t[r][0]-t[r][1]+t[r][2]);
        U[r*4+3] = t[r][2];
    }
    int kc = ci>>5, c5 = ci&31, ks = c5>>4, cc = c5&15;
    int lane = (co&7)*4 + ((cc>>1)&3);
    int r    = ((co>>3)&1) + ((cc>>3)&1)*2;
    int mt   = (co>>4)&7, cb = co>>7;
    size_t boff = ((size_t)(cb*16 + kc))*4096 + (size_t)(((ks*8+mt)*32+lane)<<3) + r*2 + (cc&1);
    #pragma unroll
    for (int u = 0; u < 16; u++)
        g_wg[boff + (size_t)u*262144] = __float2half_rn(U[u]);
}

// ---------------- input transform: D = B^T x B * s, cp.async padded planes ----------------
// g_d word layout: [b][u][cipair(256)][tile(1024)], word = f16x2 (ci even, ci odd)
__global__ void dtrans_kernel(const float* __restrict__ x){
    __shared__ float sp[2*66*PSTR];        // two padded planes, 38016 B
    int cp = blockIdx.x, b = blockIdx.y, tid = threadIdx.x;
    const float* x0 = x + ((size_t)(b*512 + cp*2))*NPIX;
    const float* x1 = x0 + NPIX;
    float s0 = g_s[b*512 + cp*2];
    float s1 = g_s[b*512 + cp*2 + 1];

    // zero-fill both planes
    float4 z = make_float4(0.f,0.f,0.f,0.f);
    for (int i = tid; i < 2*66*PSTR/4; i += 256) ((float4*)sp)[i] = z;
    __syncthreads();

    // bulk interior load: image row ir -> spad row ir+1, image col c -> spad col c+4
    // 2 planes * 64 rows * 16 chunks of 16 bytes = 2048 cp.async ops
    unsigned spu = (unsigned)__cvta_generic_to_shared(sp);
    #pragma unroll
    for (int k = 0; k < 8; k++){
        int t = tid + k*256;               // 0..2047
        int p  = t >> 10;
        int rm = t & 1023;
        int ir = rm >> 4, ch = rm & 15;
        unsigned dst = spu + (unsigned)((p*66*PSTR + (ir+1)*PSTR + 4 + ch*4)*4);
        const float* src = (p ? x1 : x0) + ir*64 + ch*4;
        asm volatile("cp.async.cg.shared.global [%0], [%1], 16;" :: "r"(dst), "l"(src));
    }
    asm volatile("cp.async.commit_group;");
    asm volatile("cp.async.wait_group 0;");
    __syncthreads();

    const float* sp0 = sp;
    const float* sp1 = sp + 66*PSTR;

    auto tilepack = [&](int i, int j, uint32_t* outp){
        float dx[4][4], dy[4][4];
        int base = (2*i)*PSTR + 2*j + 3;   // spad row 2i (image row 2i-1), col 2j+3 (image col 2j-1)
        #pragma unroll
        for (int rr = 0; rr < 4; rr++)
            #pragma unroll
            for (int cc = 0; cc < 4; cc++){
                dx[rr][cc] = sp0[base + rr*PSTR + cc] * s0;
                dy[rr][cc] = sp1[base + rr*PSTR + cc] * s1;
            }
        float tx[4][4], ty[4][4];
        #pragma unroll
        for (int c = 0; c < 4; c++){
            tx[0][c] = dx[0][c] - dx[2][c];  ty[0][c] = dy[0][c] - dy[2][c];
            tx[1][c] = dx[1][c] + dx[2][c];  ty[1][c] = dy[1][c] + dy[2][c];
            tx[2][c] = dx[2][c] - dx[1][c];  ty[2][c] = dy[2][c] - dy[1][c];
            tx[3][c] = dx[1][c] - dx[3][c];  ty[3][c] = dy[1][c] - dy[3][c];
        }
        #pragma unroll
        for (int r = 0; r < 4; r++){
            __half2 h0 = __floats2half2_rn(tx[r][0] - tx[r][2], ty[r][0] - ty[r][2]);
            __half2 h1 = __floats2half2_rn(tx[r][1] + tx[r][2], ty[r][1] + ty[r][2]);
            __half2 h2 = __floats2half2_rn(tx[r][2] - tx[r][1], ty[r][2] - ty[r][1]);
            __half2 h3 = __floats2half2_rn(tx[r][1] - tx[r][3], ty[r][1] - ty[r][3]);
            outp[r*4+0] = *(uint32_t*)&h0;
            outp[r*4+1] = *(uint32_t*)&h1;
            outp[r*4+2] = *(uint32_t*)&h2;
            outp[r*4+3] = *(uint32_t*)&h3;
        }
    };

    #pragma unroll
    for (int pp = 0; pp < 2; pp++){
        int q = pp*256 + tid;              // tile-pair index: tiles 2q, 2q+1
        int i = q >> 4, j0 = (q & 15)*2;
        uint32_t ua[16], ub[16];
        tilepack(i, j0,   ua);
        tilepack(i, j0+1, ub);
        size_t gbase = ((size_t)(b*16)*256 + cp)*1024 + 2*q;
        #pragma unroll
        for (int u = 0; u < 16; u++)
            *(uint2*)&g_d[gbase + (size_t)u*262144] = make_uint2(ua[u], ub[u]);
    }
}

// ---------------- GEMM: fp16 m16n8k16, fp32 accum, persistent CTAs, rolling 3-stage ----------------
__device__ __forceinline__ void mma_f16(float* c, uint32_t a0,uint32_t a1,uint32_t a2,uint32_t a3,
                                        uint32_t b0,uint32_t b1){
    asm volatile("mma.sync.aligned.m16n8k16.row.col.f32.f16.f16.f32 "
        "{%0,%1,%2,%3}, {%4,%5,%6,%7}, {%8,%9}, {%0,%1,%2,%3};"
        : "+f"(c[0]), "+f"(c[1]), "+f"(c[2]), "+f"(c[3])
        : "r"(a0), "r"(a1), "r"(a2), "r"(a3), "r"(b0), "r"(b1));
}

__global__ __launch_bounds__(256,2) void gemm_kernel(){
    extern __shared__ char smem[];
    const int tid  = threadIdx.x;
    const int lane = tid & 31;
    const int warp = tid >> 5;
    const int wm   = warp >> 2;       // co half (64)
    const int wn   = warp & 3;        // tile quarter (32)
    const int bx   = blockIdx.x;

    unsigned sm_u = (unsigned)__cvta_generic_to_shared(smem);

    // work list: wk = bx + j*GEMM_GRID, j < njobs ; wk -> (x=wk&31, ub=wk>>5)
    const int njobs = (8192 - bx + GEMM_GRID - 1) / GEMM_GRID;
    const int totg  = njobs * 8;      // total load-groups with real data

    // issue loads for global group g (tile j = g>>3, kc = g&7) into stage s
    auto issue = [&](int g, int s){
        int jw = g >> 3, kc = g & 7;
        int wk = bx + jw * GEMM_GRID;
        int x = wk & 31, ub = wk >> 5;
        int cb = x >> 3, nb = x & 7;
        const uint4* dsrc = (const uint4*)g_d + (size_t)ub*65536 + (size_t)(nb*32);
        const uint4* wsrc = (const uint4*)g_wg + (size_t)(ub & 15)*32768 + (size_t)cb*8192;
        unsigned base = sm_u + (unsigned)(s * STAGE_B);
        #pragma unroll
        for (int k = 0; k < 4; k++){
            int idx = tid + k*256;        // 0..1023
            int cp = idx >> 5, q = idx & 31;
            asm volatile("cp.async.cg.shared.global [%0], [%1], 16;"
                         :: "r"(base + (unsigned)((cp*DSTR + q*4)*4)),
                            "l"(dsrc + (size_t)(kc*32 + cp)*256 + q));
        }
        #pragma unroll
        for (int k = 0; k < 4; k++){
            int idx = tid + k*256;        // 0..1023
            asm volatile("cp.async.cg.shared.global [%0], [%1], 16;"
                         :: "r"(base + (unsigned)(DCH_B + idx*16)), "l"(wsrc + kc*1024 + idx));
        }
    };

    // prologue: fill two groups
    issue(0, 0);
    asm volatile("cp.async.commit_group;");
    issue(1, 1);
    asm volatile("cp.async.commit_group;");
    int gl = 2, sl = 2;                   // next group to issue, its stage
    int sc = 0;                           // consume stage

    for (int jw = 0; jw < njobs; jw++){
        int wk = bx + jw * GEMM_GRID;
        int x = wk & 31, ub = wk >> 5;
        int cb = x >> 3, nb = x & 7;
        int tile0 = nb * 128;

        float acc[4][4][4];
        #pragma unroll
        for (int i=0;i<4;i++)
          #pragma unroll
          for (int j=0;j<4;j++)
            #pragma unroll
            for (int k=0;k<4;k++) acc[i][j][k]=0.f;

        for (int kc = 0; kc < 8; kc++){
            asm volatile("cp.async.wait_group 1;");
            __syncthreads();

            const uint32_t* xb = (const uint32_t*)(smem + sc*STAGE_B) + wn*32 + (lane >> 2);
            const float4*  w4 = (const float4*)(smem + sc*STAGE_B + DCH_B);

            #pragma unroll
            for (int ks = 0; ks < 4; ks++){   // 4 x k16 within 64-ci chunk
                const uint32_t* xp = xb + (ks*8 + (lane & 3)) * DSTR;
                uint32_t bf[4][2];
                #pragma unroll
                for (int nt = 0; nt < 4; nt++){
                    bf[nt][0] = xp[nt*8];
                    bf[nt][1] = xp[nt*8 + 4*DSTR];
                }
                #pragma unroll
                for (int mt = 0; mt < 4; mt++){
                    float4 a = w4[(ks>>1)*512 + (((ks&1)*8 + wm*4 + mt)*32 + lane)];
                    uint32_t a0=__float_as_uint(a.x), a1=__float_as_uint(a.y),
                             a2=__float_as_uint(a.z), a3=__float_as_uint(a.w);
                    #pragma unroll
                    for (int nt = 0; nt < 4; nt++)
                        mma_f16(acc[mt][nt], a0,a1,a2,a3, bf[nt][0], bf[nt][1]);
                }
            }
            // rolling prefetch 2 groups ahead (crosses tile boundaries).
            // stage sl was last read at group gl-3 (== sl mod 3), whose readers
            // passed this iteration's top-of-loop barrier -> safe without extra barrier.
            if (gl < totg) issue(gl, sl);
            asm volatile("cp.async.commit_group;");   // empty group in the tail keeps wait-1 accounting
            gl++;
            if (++sl == 3) sl = 0;
            if (++sc == 3) sc = 0;
        }

        // epilogue: write M as fp16 (regs only; overlaps already-issued next-tile loads)
        #pragma unroll
        for (int mt = 0; mt < 4; mt++){
            int co = cb*128 + wm*64 + mt*16 + (lane >> 2);
            size_t rb = ((size_t)ub*512 + co)*1024;
            #pragma unroll
            for (int nt = 0; nt < 4; nt++){
                int tile = tile0 + wn*32 + nt*8 + (lane & 3)*2;
                __half2 v0 = __floats2half2_rn(acc[mt][nt][0], acc[mt][nt][1]);
                __half2 v1 = __floats2half2_rn(acc[mt][nt][2], acc[mt][nt][3]);
                *(__half2*)(g_m + rb + tile)          = v0;
                *(__half2*)(g_m + rb + 8*1024 + tile) = v1;
            }
        }
    }
}

// ---------------- inverse transform: out = A^T M A * dscale (4 tiles/thread, uint2 loads) ----------------
__global__ void inv_kernel(float* __restrict__ out){
    int co = blockIdx.x, b = blockIdx.y, tid = threadIdx.x;
    float ds = g_dscale[b*512 + co];
    const uint2* mp = (const uint2*)(g_m + ((size_t)(b*16)*512 + co)*1024);  // u-stride 131072 uint2
    float* op = out + ((size_t)(b*512 + co))*NPIX;

    int p = tid;                           // 4-tile group: tiles 4p..4p+3
    int i = p >> 3, j0 = (p & 7) * 8;      // output row pair i, col base

    float2 ma[16], mb[16];                 // ma: tiles 4p,4p+1  mb: tiles 4p+2,4p+3
    #pragma unroll
    for (int u = 0; u < 16; u++){
        uint2 v = mp[(size_t)u*131072 + p];
        ma[u] = __half22float2(*(__half2*)&v.x);
        mb[u] = __half22float2(*(__half2*)&v.y);
    }

    float2 p0a[4], p1a[4], p0b[4], p1b[4];
    #pragma unroll
    for (int c = 0; c < 4; c++){
        p0a[c] = make_float2(ma[c].x + ma[4+c].x + ma[8+c].x,
                             ma[c].y + ma[4+c].y + ma[8+c].y);
        p1a[c] = make_float2(ma[4+c].x - ma[8+c].x - ma[12+c].x,
                             ma[4+c].y - ma[8+c].y - ma[12+c].y);
        p0b[c] = make_float2(mb[c].x + mb[4+c].x + mb[8+c].x,
                             mb[c].y + mb[4+c].y + mb[8+c].y);
        p1b[c] = make_float2(mb[4+c].x - mb[8+c].x - mb[12+c].x,
                             mb[4+c].y - mb[8+c].y - mb[12+c].y);
    }
    float4 r0a = make_float4((p0a[0].x+p0a[1].x+p0a[2].x)*ds, (p0a[1].x-p0a[2].x-p0a[3].x)*ds,
                             (p0a[0].y+p0a[1].y+p0a[2].y)*ds, (p0a[1].y-p0a[2].y-p0a[3].y)*ds);
    float4 r1a = make_float4((p1a[0].x+p1a[1].x+p1a[2].x)*ds, (p1a[1].x-p1a[2].x-p1a[3].x)*ds,
                             (p1a[0].y+p1a[1].y+p1a[2].y)*ds, (p1a[1].y-p1a[2].y-p1a[3].y)*ds);
    float4 r0b = make_float4((p0b[0].x+p0b[1].x+p0b[2].x)*ds, (p0b[1].x-p0b[2].x-p0b[3].x)*ds,
                             (p0b[0].y+p0b[1].y+p0b[2].y)*ds, (p0b[1].y-p0b[2].y-p0b[3].y)*ds);
    float4 r1b = make_float4((p1b[0].x+p1b[1].x+p1b[2].x)*ds, (p1b[1].x-p1b[2].x-p1b[3].x)*ds,
                             (p1b[0].y+p1b[1].y+p1b[2].y)*ds, (p1b[1].y-p1b[2].y-p1b[3].y)*ds);

    *(float4*)(op + (2*i)*64   + j0)     = r0a;
    *(float4*)(op + (2*i)*64   + j0 + 4) = r0b;
    *(float4*)(op + (2*i+1)*64 + j0)     = r1a;
    *(float4*)(op + (2*i+1)*64 + j0 + 4) = r1b;
}

// ---------------- launcher ----------------
extern "C" void kernel_launch(void* const* d_in, const int* in_sizes, int n_in,
                              void* d_out, int out_size){
    const float* input      = (const float*)d_in[0];
    const float* style      = (const float*)d_in[1];
    const float* weight     = (const float*)d_in[2];
    const float* mod_weight = (const float*)d_in[3];
    const float* mod_bias   = (const float*)d_in[4];
    float* out = (float*)d_out;

    cudaFuncSetAttribute(gemm_kernel, cudaFuncAttributeMaxDynamicSharedMemorySize, GEMM_SMEM);

    // order chosen so gemm lands in the ncu capture slot (deps remain valid:
    // demod only feeds inv)
    mod_kernel    <<<16, 512>>>(style, mod_weight, mod_bias);
    wtrans_kernel <<<1024, 256>>>(weight);
    dtrans_kernel <<<dim3(256,16), 256>>>(input);
    gemm_kernel   <<<GEMM_GRID, 256, GEMM_SMEM>>>();
    demod_kernel  <<<16, 512>>>();
    inv_kernel    <<<dim3(512,16), 256>>>(out);
}

// round 14
// speedup vs baseline: 3.0603x; 1.2046x over previous
#include <cuda_runtime.h>
#include <cuda_fp16.h>
#include <cstdint>
#include <cstddef>

#define BATCH 16
#define CIN   512
#define COUT  512
#define NPIX  4096
#define MOD_SCALE  0.044194173824159216f
#define CONV_SCALE 0.014731391274719739f

// Winograd F(2x2,3x3): 1024 tiles/image, 16 transform points (u)
// GEMM per (u,b): M_u[512co,1024t] = W_u[512co,512ci] * D_u[512ci,1024t]
// Persistent CTAs: 304 resident, rolling 3-stage cp.async across tiles.

#define DSTR   136                          // 128 tiles + 8 pad words (8 mod 32 -> conflict-free)
#define DCH_B  (32*DSTR*4)                  // 17408 B per D stage (32 cipairs)
#define WCH_B  16384                        // 64ci x 128co fp16
#define STAGE_B (DCH_B + WCH_B)             // 33792 B
#define GEMM_SMEM (3*STAGE_B)               // 101376 B
#define GEMM_GRID 304

#define PSTR 72                             // dtrans smem plane stride (floats)

// ---------------- device scratch ----------------
__device__ float g_s[BATCH*CIN];
__device__ float g_wsq[COUT*CIN];
__device__ __align__(128) __half   g_wg[16*4*16*4096];                 // 8 MB transformed W, frag-packed
__device__ __align__(128) uint32_t g_d[(size_t)16*16*256*1024];        // 268 MB transformed input (f16x2 ci-pairs)
__device__ __align__(128) __half   g_m[(size_t)16*16*512*1024];        // 268 MB GEMM output M

// ---------------- fused pre-pass: blocks 0..15 = mod, blocks 16..527 = wtrans ----------------
__global__ __launch_bounds__(512) void pre_kernel(const float* __restrict__ style,
                                                  const float* __restrict__ mod_weight,
                                                  const float* __restrict__ mod_bias,
                                                  const float* __restrict__ w){
    int blk = blockIdx.x, tid = threadIdx.x;
    if (blk < 16){
        // s[b][ci] = style @ (mod_weight*MOD_SCALE)^T + bias
        __shared__ float st[512];
        int b = blk;
        st[tid] = style[b*512 + tid];
        __syncthreads();
        const float* wr = mod_weight + tid*512;
        float acc = 0.f;
        #pragma unroll 8
        for (int j = 0; j < 512; j++) acc = fmaf(st[j], wr[j], acc);
        g_s[b*512 + tid] = acc * MOD_SCALE + mod_bias[tid];
        return;
    }
    // weight transform U = G g G^T (frag-packed fp16) + fused wsq
    int i = (blk - 16)*512 + tid;                  // 262144 = co*512+ci
    int co = i >> 9, ci = i & 511;
    const float* p = w + (size_t)i*9;
    float g[3][3];
    float sq = 0.f;
    #pragma unroll
    for (int r = 0; r < 3; r++)
        #pragma unroll
        for (int c = 0; c < 3; c++){ g[r][c] = p[r*3+c]; sq = fmaf(g[r][c], g[r][c], sq); }
    g_wsq[i] = sq;
    float t[4][3];
    #pragma unroll
    for (int c = 0; c < 3; c++){
        t[0][c] = g[0][c];
        t[1][c] = 0.5f*(g[0][c]+g[1][c]+g[2][c]);
        t[2][c] = 0.5f*(g[0][c]-g[1][c]+g[2][c]);
        t[3][c] = g[2][c];
    }
    float U[16];
    #pragma unroll
    for (int r = 0; r < 4; r++){
        U[r*4+0] = t[r][0];
        U[r*4+1] = 0.5f*(t[r][0]+t[r][1]+t[r][2]);
        U[r*4+2] = 0.5f*(t[r][0]-t[r][1]+t[r][2]);
        U[r*4+3] = t[r][2];
    }
    int kc = ci>>5, c5 = ci&31, ks = c5>>4, cc = c5&15;
    int lane = (co&7)*4 + ((cc>>1)&3);
    int r    = ((co>>3)&1) + ((cc>>3)&1)*2;
    int mt   = (co>>4)&7, cb = co>>7;
    size_t boff = ((size_t)(cb*16 + kc))*4096 + (size_t)(((ks*8+mt)*32+lane)<<3) + r*2 + (cc&1);
    #pragma unroll
    for (int u = 0; u < 16; u++)
        g_wg[boff + (size_t)u*262144] = __float2half_rn(U[u]);
}

// ---------------- input transform: D = B^T x B * s, cp.async padded planes ----------------
// g_d word layout: [b][u][cipair(256)][tile(1024)], word = f16x2 (ci even, ci odd)
__global__ void dtrans_kernel(const float* __restrict__ x){
    __shared__ float sp[2*66*PSTR];        // two padded planes, 38016 B
    int cp = blockIdx.x, b = blockIdx.y, tid = threadIdx.x;
    const float* x0 = x + ((size_t)(b*512 + cp*2))*NPIX;
    const float* x1 = x0 + NPIX;
    float s0 = g_s[b*512 + cp*2];
    float s1 = g_s[b*512 + cp*2 + 1];

    // zero-fill both planes
    float4 z = make_float4(0.f,0.f,0.f,0.f);
    for (int i = tid; i < 2*66*PSTR/4; i += 256) ((float4*)sp)[i] = z;
    __syncthreads();

    // bulk interior load: image row ir -> spad row ir+1, image col c -> spad col c+4
    unsigned spu = (unsigned)__cvta_generic_to_shared(sp);
    #pragma unroll
    for (int k = 0; k < 8; k++){
        int t = tid + k*256;               // 0..2047
        int p  = t >> 10;
        int rm = t & 1023;
        int ir = rm >> 4, ch = rm & 15;
        unsigned dst = spu + (unsigned)((p*66*PSTR + (ir+1)*PSTR + 4 + ch*4)*4);
        const float* src = (p ? x1 : x0) + ir*64 + ch*4;
        asm volatile("cp.async.cg.shared.global [%0], [%1], 16;" :: "r"(dst), "l"(src));
    }
    asm volatile("cp.async.commit_group;");
    asm volatile("cp.async.wait_group 0;");
    __syncthreads();

    const float* sp0 = sp;
    const float* sp1 = sp + 66*PSTR;

    auto tilepack = [&](int i, int j, uint32_t* outp){
        float dx[4][4], dy[4][4];
        int base = (2*i)*PSTR + 2*j + 3;
        #pragma unroll
        for (int rr = 0; rr < 4; rr++)
            #pragma unroll
            for (int cc = 0; cc < 4; cc++){
                dx[rr][cc] = sp0[base + rr*PSTR + cc] * s0;
                dy[rr][cc] = sp1[base + rr*PSTR + cc] * s1;
            }
        float tx[4][4], ty[4][4];
        #pragma unroll
        for (int c = 0; c < 4; c++){
            tx[0][c] = dx[0][c] - dx[2][c];  ty[0][c] = dy[0][c] - dy[2][c];
            tx[1][c] = dx[1][c] + dx[2][c];  ty[1][c] = dy[1][c] + dy[2][c];
            tx[2][c] = dx[2][c] - dx[1][c];  ty[2][c] = dy[2][c] - dy[1][c];
            tx[3][c] = dx[1][c] - dx[3][c];  ty[3][c] = dy[1][c] - dy[3][c];
        }
        #pragma unroll
        for (int r = 0; r < 4; r++){
            __half2 h0 = __floats2half2_rn(tx[r][0] - tx[r][2], ty[r][0] - ty[r][2]);
            __half2 h1 = __floats2half2_rn(tx[r][1] + tx[r][2], ty[r][1] + ty[r][2]);
            __half2 h2 = __floats2half2_rn(tx[r][2] - tx[r][1], ty[r][2] - ty[r][1]);
            __half2 h3 = __floats2half2_rn(tx[r][1] - tx[r][3], ty[r][1] - ty[r][3]);
            outp[r*4+0] = *(uint32_t*)&h0;
            outp[r*4+1] = *(uint32_t*)&h1;
            outp[r*4+2] = *(uint32_t*)&h2;
            outp[r*4+3] = *(uint32_t*)&h3;
        }
    };

    #pragma unroll
    for (int pp = 0; pp < 2; pp++){
        int q = pp*256 + tid;              // tile-pair index: tiles 2q, 2q+1
        int i = q >> 4, j0 = (q & 15)*2;
        uint32_t ua[16], ub[16];
        tilepack(i, j0,   ua);
        tilepack(i, j0+1, ub);
        size_t gbase = ((size_t)(b*16)*256 + cp)*1024 + 2*q;
        #pragma unroll
        for (int u = 0; u < 16; u++)
            *(uint2*)&g_d[gbase + (size_t)u*262144] = make_uint2(ua[u], ub[u]);
    }
}

// ---------------- GEMM: fp16 m16n8k16, fp32 accum, persistent CTAs, rolling 3-stage ----------------
__device__ __forceinline__ void mma_f16(float* c, uint32_t a0,uint32_t a1,uint32_t a2,uint32_t a3,
                                        uint32_t b0,uint32_t b1){
    asm volatile("mma.sync.aligned.m16n8k16.row.col.f32.f16.f16.f32 "
        "{%0,%1,%2,%3}, {%4,%5,%6,%7}, {%8,%9}, {%0,%1,%2,%3};"
        : "+f"(c[0]), "+f"(c[1]), "+f"(c[2]), "+f"(c[3])
        : "r"(a0), "r"(a1), "r"(a2), "r"(a3), "r"(b0), "r"(b1));
}

__global__ __launch_bounds__(256,2) void gemm_kernel(){
    extern __shared__ char smem[];
    const int tid  = threadIdx.x;
    const int lane = tid & 31;
    const int warp = tid >> 5;
    const int wm   = warp >> 2;       // co half (64)
    const int wn   = warp & 3;        // tile quarter (32)
    const int bx   = blockIdx.x;

    unsigned sm_u = (unsigned)__cvta_generic_to_shared(smem);

    const int njobs = (8192 - bx + GEMM_GRID - 1) / GEMM_GRID;
    const int totg  = njobs * 8;

    auto issue = [&](int g, int s){
        int jw = g >> 3, kc = g & 7;
        int wk = bx + jw * GEMM_GRID;
        int x = wk & 31, ub = wk >> 5;
        int cb = x >> 3, nb = x & 7;
        const uint4* dsrc = (const uint4*)g_d + (size_t)ub*65536 + (size_t)(nb*32);
        const uint4* wsrc = (const uint4*)g_wg + (size_t)(ub & 15)*32768 + (size_t)cb*8192;
        unsigned base = sm_u + (unsigned)(s * STAGE_B);
        #pragma unroll
        for (int k = 0; k < 4; k++){
            int idx = tid + k*256;
            int cp = idx >> 5, q = idx & 31;
            asm volatile("cp.async.cg.shared.global [%0], [%1], 16;"
                         :: "r"(base + (unsigned)((cp*DSTR + q*4)*4)),
                            "l"(dsrc + (size_t)(kc*32 + cp)*256 + q));
        }
        #pragma unroll
        for (int k = 0; k < 4; k++){
            int idx = tid + k*256;
            asm volatile("cp.async.cg.shared.global [%0], [%1], 16;"
                         :: "r"(base + (unsigned)(DCH_B + idx*16)), "l"(wsrc + kc*1024 + idx));
        }
    };

    issue(0, 0);
    asm volatile("cp.async.commit_group;");
    issue(1, 1);
    asm volatile("cp.async.commit_group;");
    int gl = 2, sl = 2;
    int sc = 0;

    for (int jw = 0; jw < njobs; jw++){
        int wk = bx + jw * GEMM_GRID;
        int x = wk & 31, ub = wk >> 5;
        int cb = x >> 3, nb = x & 7;
        int tile0 = nb * 128;

        float acc[4][4][4];
        #pragma unroll
        for (int i=0;i<4;i++)
          #pragma unroll
          for (int j=0;j<4;j++)
            #pragma unroll
            for (int k=0;k<4;k++) acc[i][j][k]=0.f;

        for (int kc = 0; kc < 8; kc++){
            asm volatile("cp.async.wait_group 1;");
            __syncthreads();

            const uint32_t* xb = (const uint32_t*)(smem + sc*STAGE_B) + wn*32 + (lane >> 2);
            const float4*  w4 = (const float4*)(smem + sc*STAGE_B + DCH_B);

            #pragma unroll
            for (int ks = 0; ks < 4; ks++){
                const uint32_t* xp = xb + (ks*8 + (lane & 3)) * DSTR;
                uint32_t bf[4][2];
                #pragma unroll
                for (int nt = 0; nt < 4; nt++){
                    bf[nt][0] = xp[nt*8];
                    bf[nt][1] = xp[nt*8 + 4*DSTR];
                }
                #pragma unroll
                for (int mt = 0; mt < 4; mt++){
                    float4 a = w4[(ks>>1)*512 + (((ks&1)*8 + wm*4 + mt)*32 + lane)];
                    uint32_t a0=__float_as_uint(a.x), a1=__float_as_uint(a.y),
                             a2=__float_as_uint(a.z), a3=__float_as_uint(a.w);
                    #pragma unroll
                    for (int nt = 0; nt < 4; nt++)
                        mma_f16(acc[mt][nt], a0,a1,a2,a3, bf[nt][0], bf[nt][1]);
                }
            }
            if (gl < totg) issue(gl, sl);
            asm volatile("cp.async.commit_group;");
            gl++;
            if (++sl == 3) sl = 0;
            if (++sc == 3) sc = 0;
        }

        #pragma unroll
        for (int mt = 0; mt < 4; mt++){
            int co = cb*128 + wm*64 + mt*16 + (lane >> 2);
            size_t rb = ((size_t)ub*512 + co)*1024;
            #pragma unroll
            for (int nt = 0; nt < 4; nt++){
                int tile = tile0 + wn*32 + nt*8 + (lane & 3)*2;
                __half2 v0 = __floats2half2_rn(acc[mt][nt][0], acc[mt][nt][1]);
                __half2 v1 = __floats2half2_rn(acc[mt][nt][2], acc[mt][nt][3]);
                *(__half2*)(g_m + rb + tile)          = v0;
                *(__half2*)(g_m + rb + 8*1024 + tile) = v1;
            }
        }
    }
}

// ---------------- inverse transform + fused demod: out = (A^T M A) * dscale ----------------
// grid (256, 16): 2 co per CTA; 128 threads per co, 8 tiles/thread via uint4 loads.
__global__ __launch_bounds__(256) void inv_kernel(float* __restrict__ out){
    __shared__ float red[256];
    int blk = blockIdx.x, b = blockIdx.y, tid = threadIdx.x;
    int half = tid >> 7;                   // co sub-index
    int lt   = tid & 127;
    int co = blk*2 + half;

    // fused demod: ds = CONV_SCALE / sqrt(CONV_SCALE^2 * sum_ci s^2*wsq + 1e-8)
    float partial = 0.f;
    #pragma unroll
    for (int k = 0; k < 4; k++){
        int ci = lt + k*128;
        float sv = g_s[b*512 + ci];
        partial = fmaf(sv*sv, g_wsq[co*512 + ci], partial);
    }
    red[tid] = partial;
    __syncthreads();
    #pragma unroll
    for (int off = 64; off > 0; off >>= 1){
        if (lt < off) red[tid] += red[tid + off];
        __syncthreads();
    }
    float ds = CONV_SCALE / sqrtf(CONV_SCALE*CONV_SCALE*red[half*128] + 1e-8f);

    // 8 tiles per thread: tiles 8p..8p+7 (one uint4 per u)
    int p = lt;
    const uint4* mp = (const uint4*)(g_m + ((size_t)(b*16)*512 + co)*1024);  // u-stride 65536 uint4
    uint4 raw[16];
    #pragma unroll
    for (int u = 0; u < 16; u++) raw[u] = mp[(size_t)u*65536 + p];

    float* op = out + ((size_t)(b*512 + co))*NPIX;
    int i = p >> 2, jb = (p & 3)*16;       // row pair i, col base 16*(p&3)

    #pragma unroll
    for (int sl = 0; sl < 4; sl++){
        float2 m[16];
        #pragma unroll
        for (int u = 0; u < 16; u++){
            uint32_t w = (sl==0) ? raw[u].x : (sl==1) ? raw[u].y : (sl==2) ? raw[u].z : raw[u].w;
            m[u] = __half22float2(*(__half2*)&w);
        }
        float2 p0[4], p1[4];
        #pragma unroll
        for (int c = 0; c < 4; c++){
            p0[c] = make_float2(m[c].x + m[4+c].x + m[8+c].x,
                                m[c].y + m[4+c].y + m[8+c].y);
            p1[c] = make_float2(m[4+c].x - m[8+c].x - m[12+c].x,
                                m[4+c].y - m[8+c].y - m[12+c].y);
        }
        float4 r0 = make_float4((p0[0].x+p0[1].x+p0[2].x)*ds, (p0[1].x-p0[2].x-p0[3].x)*ds,
                                (p0[0].y+p0[1].y+p0[2].y)*ds, (p0[1].y-p0[2].y-p0[3].y)*ds);
        float4 r1 = make_float4((p1[0].x+p1[1].x+p1[2].x)*ds, (p1[1].x-p1[2].x-p1[3].x)*ds,
                                (p1[0].y+p1[1].y+p1[2].y)*ds, (p1[1].y-p1[2].y-p1[3].y)*ds);
        *(float4*)(op + (2*i)*64   + jb + 4*sl) = r0;
        *(float4*)(op + (2*i+1)*64 + jb + 4*sl) = r1;
    }
}

// ---------------- launcher ----------------
extern "C" void kernel_launch(void* const* d_in, const int* in_sizes, int n_in,
                              void* d_out, int out_size){
    const float* input      = (const float*)d_in[0];
    const float* style      = (const float*)d_in[1];
    const float* weight     = (const float*)d_in[2];
    const float* mod_weight = (const float*)d_in[3];
    const float* mod_bias   = (const float*)d_in[4];
    float* out = (float*)d_out;

    cudaFuncSetAttribute(gemm_kernel, cudaFuncAttributeMaxDynamicSharedMemorySize, GEMM_SMEM);

    pre_kernel    <<<528, 512>>>(style, mod_weight, mod_bias, weight);
    dtrans_kernel <<<dim3(256,16), 256>>>(input);
    gemm_kernel   <<<GEMM_GRID, 256, GEMM_SMEM>>>();
    inv_kernel    <<<dim3(256,16), 256>>>(out);
}

// round 15
// speedup vs baseline: 3.0853x; 1.0082x over previous
#include <cuda_runtime.h>
#include <cuda_fp16.h>
#include <cstdint>
#include <cstddef>

#define BATCH 16
#define CIN   512
#define COUT  512
#define NPIX  4096
#define MOD_SCALE  0.044194173824159216f
#define CONV_SCALE 0.014731391274719739f

// Winograd F(2x2,3x3): 1024 tiles/image, 16 transform points (u)
// GEMM per (u,b): M_u[512co,1024t] = W_u[512co,512ci] * D_u[512ci,1024t]
// Persistent CTAs: 304 resident, rolling 3-stage cp.async across tiles.

#define DSTR   136                          // 128 tiles + 8 pad words (8 mod 32 -> conflict-free)
#define DCH_B  (32*DSTR*4)                  // 17408 B per D stage (32 cipairs)
#define WCH_B  16384                        // 64ci x 128co fp16
#define STAGE_B (DCH_B + WCH_B)             // 33792 B
#define GEMM_SMEM (3*STAGE_B)               // 101376 B
#define GEMM_GRID 304

#define PSTR 72                             // dtrans smem plane stride (floats)

// ---------------- device scratch ----------------
__device__ float g_s[BATCH*CIN];
__device__ float g_wsq[COUT*CIN];
__device__ __align__(128) __half   g_wg[16*4*16*4096];                 // 8 MB transformed W, frag-packed
__device__ __align__(128) uint32_t g_d[(size_t)16*16*256*1024];        // 268 MB transformed input (f16x2 ci-pairs)
__device__ __align__(128) __half   g_m[(size_t)16*16*512*1024];        // 268 MB GEMM output M

// ---------------- mod: s[b][ci] = style @ (mod_weight*MOD_SCALE)^T + bias ----------------
__global__ __launch_bounds__(512) void mod_kernel(const float* __restrict__ style,
                                                  const float* __restrict__ mod_weight,
                                                  const float* __restrict__ mod_bias){
    __shared__ float st[512];
    int b = blockIdx.x, t = threadIdx.x;
    st[t] = style[b*512 + t];
    __syncthreads();
    const float* wr = mod_weight + t*512;
    float acc = 0.f;
    #pragma unroll 8
    for (int j = 0; j < 512; j++) acc = fmaf(st[j], wr[j], acc);
    g_s[b*512 + t] = acc * MOD_SCALE + mod_bias[t];
}

// ---------------- dtrans (grid y<16) + fused wtrans (grid y>=16) ----------------
// dtrans: D = B^T x B * s, cp.async padded planes.
//   g_d word layout: [b][u][cipair(256)][tile(1024)], word = f16x2 (ci even, ci odd)
// wtrans: U = G g G^T (frag-packed fp16) + fused wsq. Runs concurrently on spare blocks.
__global__ __launch_bounds__(256) void dtrans_kernel(const float* __restrict__ x,
                                                     const float* __restrict__ w){
    __shared__ float sp[2*66*PSTR];        // two padded planes, 38016 B
    int tid = threadIdx.x;

    if (blockIdx.y >= 16){
        // ---- wtrans ----
        int blk = (blockIdx.y - 16)*256 + blockIdx.x;   // 0..1023
        int i = blk*256 + tid;                          // 262144 = co*512+ci
        int co = i >> 9, ci = i & 511;
        const float* p = w + (size_t)i*9;
        float g[3][3];
        float sq = 0.f;
        #pragma unroll
        for (int r = 0; r < 3; r++)
            #pragma unroll
            for (int c = 0; c < 3; c++){ g[r][c] = p[r*3+c]; sq = fmaf(g[r][c], g[r][c], sq); }
        g_wsq[i] = sq;
        float t[4][3];
        #pragma unroll
        for (int c = 0; c < 3; c++){
            t[0][c] = g[0][c];
            t[1][c] = 0.5f*(g[0][c]+g[1][c]+g[2][c]);
            t[2][c] = 0.5f*(g[0][c]-g[1][c]+g[2][c]);
            t[3][c] = g[2][c];
        }
        float U[16];
        #pragma unroll
        for (int r = 0; r < 4; r++){
            U[r*4+0] = t[r][0];
            U[r*4+1] = 0.5f*(t[r][0]+t[r][1]+t[r][2]);
            U[r*4+2] = 0.5f*(t[r][0]-t[r][1]+t[r][2]);
            U[r*4+3] = t[r][2];
        }
        int kc = ci>>5, c5 = ci&31, ks = c5>>4, cc = c5&15;
        int lane = (co&7)*4 + ((cc>>1)&3);
        int r    = ((co>>3)&1) + ((cc>>3)&1)*2;
        int mt   = (co>>4)&7, cb = co>>7;
        size_t boff = ((size_t)(cb*16 + kc))*4096 + (size_t)(((ks*8+mt)*32+lane)<<3) + r*2 + (cc&1);
        #pragma unroll
        for (int u = 0; u < 16; u++)
            g_wg[boff + (size_t)u*262144] = __float2half_rn(U[u]);
        return;
    }

    // ---- dtrans ----
    int cp = blockIdx.x, b = blockIdx.y;
    const float* x0 = x + ((size_t)(b*512 + cp*2))*NPIX;
    const float* x1 = x0 + NPIX;
    float s0 = g_s[b*512 + cp*2];
    float s1 = g_s[b*512 + cp*2 + 1];

    // zero-fill both planes
    float4 z = make_float4(0.f,0.f,0.f,0.f);
    for (int i = tid; i < 2*66*PSTR/4; i += 256) ((float4*)sp)[i] = z;
    __syncthreads();

    // bulk interior load: image row ir -> spad row ir+1, image col c -> spad col c+4
    unsigned spu = (unsigned)__cvta_generic_to_shared(sp);
    #pragma unroll
    for (int k = 0; k < 8; k++){
        int t = tid + k*256;               // 0..2047
        int p  = t >> 10;
        int rm = t & 1023;
        int ir = rm >> 4, ch = rm & 15;
        unsigned dst = spu + (unsigned)((p*66*PSTR + (ir+1)*PSTR + 4 + ch*4)*4);
        const float* src = (p ? x1 : x0) + ir*64 + ch*4;
        asm volatile("cp.async.cg.shared.global [%0], [%1], 16;" :: "r"(dst), "l"(src));
    }
    asm volatile("cp.async.commit_group;");
    asm volatile("cp.async.wait_group 0;");
    __syncthreads();

    const float* sp0 = sp;
    const float* sp1 = sp + 66*PSTR;

    auto tilepack = [&](int i, int j, uint32_t* outp){
        float dx[4][4], dy[4][4];
        int base = (2*i)*PSTR + 2*j + 3;
        #pragma unroll
        for (int rr = 0; rr < 4; rr++)
            #pragma unroll
            for (int cc = 0; cc < 4; cc++){
                dx[rr][cc] = sp0[base + rr*PSTR + cc] * s0;
                dy[rr][cc] = sp1[base + rr*PSTR + cc] * s1;
            }
        float tx[4][4], ty[4][4];
        #pragma unroll
        for (int c = 0; c < 4; c++){
            tx[0][c] = dx[0][c] - dx[2][c];  ty[0][c] = dy[0][c] - dy[2][c];
            tx[1][c] = dx[1][c] + dx[2][c];  ty[1][c] = dy[1][c] + dy[2][c];
            tx[2][c] = dx[2][c] - dx[1][c];  ty[2][c] = dy[2][c] - dy[1][c];
            tx[3][c] = dx[1][c] - dx[3][c];  ty[3][c] = dy[1][c] - dy[3][c];
        }
        #pragma unroll
        for (int r = 0; r < 4; r++){
            __half2 h0 = __floats2half2_rn(tx[r][0] - tx[r][2], ty[r][0] - ty[r][2]);
            __half2 h1 = __floats2half2_rn(tx[r][1] + tx[r][2], ty[r][1] + ty[r][2]);
            __half2 h2 = __floats2half2_rn(tx[r][2] - tx[r][1], ty[r][2] - ty[r][1]);
            __half2 h3 = __floats2half2_rn(tx[r][1] - tx[r][3], ty[r][1] - ty[r][3]);
            outp[r*4+0] = *(uint32_t*)&h0;
            outp[r*4+1] = *(uint32_t*)&h1;
            outp[r*4+2] = *(uint32_t*)&h2;
            outp[r*4+3] = *(uint32_t*)&h3;
        }
    };

    #pragma unroll
    for (int pp = 0; pp < 2; pp++){
        int q = pp*256 + tid;              // tile-pair index: tiles 2q, 2q+1
        int i = q >> 4, j0 = (q & 15)*2;
        uint32_t ua[16], ub[16];
        tilepack(i, j0,   ua);
        tilepack(i, j0+1, ub);
        size_t gbase = ((size_t)(b*16)*256 + cp)*1024 + 2*q;
        #pragma unroll
        for (int u = 0; u < 16; u++)
            *(uint2*)&g_d[gbase + (size_t)u*262144] = make_uint2(ua[u], ub[u]);
    }
}

// ---------------- GEMM: fp16 m16n8k16, fp32 accum, persistent CTAs, rolling 3-stage ----------------
__device__ __forceinline__ void mma_f16(float* c, uint32_t a0,uint32_t a1,uint32_t a2,uint32_t a3,
                                        uint32_t b0,uint32_t b1){
    asm volatile("mma.sync.aligned.m16n8k16.row.col.f32.f16.f16.f32 "
        "{%0,%1,%2,%3}, {%4,%5,%6,%7}, {%8,%9}, {%0,%1,%2,%3};"
        : "+f"(c[0]), "+f"(c[1]), "+f"(c[2]), "+f"(c[3])
        : "r"(a0), "r"(a1), "r"(a2), "r"(a3), "r"(b0), "r"(b1));
}

__global__ __launch_bounds__(256,2) void gemm_kernel(){
    extern __shared__ char smem[];
    const int tid  = threadIdx.x;
    const int lane = tid & 31;
    const int warp = tid >> 5;
    const int wm   = warp >> 2;       // co half (64)
    const int wn   = warp & 3;        // tile quarter (32)
    const int bx   = blockIdx.x;

    unsigned sm_u = (unsigned)__cvta_generic_to_shared(smem);

    const int njobs = (8192 - bx + GEMM_GRID - 1) / GEMM_GRID;
    const int totg  = njobs * 8;

    auto issue = [&](int g, int s){
        int jw = g >> 3, kc = g & 7;
        int wk = bx + jw * GEMM_GRID;
        int x = wk & 31, ub = wk >> 5;
        int cb = x >> 3, nb = x & 7;
        const uint4* dsrc = (const uint4*)g_d + (size_t)ub*65536 + (size_t)(nb*32);
        const uint4* wsrc = (const uint4*)g_wg + (size_t)(ub & 15)*32768 + (size_t)cb*8192;
        unsigned base = sm_u + (unsigned)(s * STAGE_B);
        #pragma unroll
        for (int k = 0; k < 4; k++){
            int idx = tid + k*256;
            int cp = idx >> 5, q = idx & 31;
            asm volatile("cp.async.cg.shared.global [%0], [%1], 16;"
                         :: "r"(base + (unsigned)((cp*DSTR + q*4)*4)),
                            "l"(dsrc + (size_t)(kc*32 + cp)*256 + q));
        }
        #pragma unroll
        for (int k = 0; k < 4; k++){
            int idx = tid + k*256;
            asm volatile("cp.async.cg.shared.global [%0], [%1], 16;"
                         :: "r"(base + (unsigned)(DCH_B + idx*16)), "l"(wsrc + kc*1024 + idx));
        }
    };

    issue(0, 0);
    asm volatile("cp.async.commit_group;");
    issue(1, 1);
    asm volatile("cp.async.commit_group;");
    int gl = 2, sl = 2;
    int sc = 0;

    for (int jw = 0; jw < njobs; jw++){
        int wk = bx + jw * GEMM_GRID;
        int x = wk & 31, ub = wk >> 5;
        int cb = x >> 3, nb = x & 7;
        int tile0 = nb * 128;

        float acc[4][4][4];
        #pragma unroll
        for (int i=0;i<4;i++)
          #pragma unroll
          for (int j=0;j<4;j++)
            #pragma unroll
            for (int k=0;k<4;k++) acc[i][j][k]=0.f;

        for (int kc = 0; kc < 8; kc++){
            asm volatile("cp.async.wait_group 1;");
            __syncthreads();

            const uint32_t* xb = (const uint32_t*)(smem + sc*STAGE_B) + wn*32 + (lane >> 2);
            const float4*  w4 = (const float4*)(smem + sc*STAGE_B + DCH_B);

            auto compute_ks = [&](int ks){
                const uint32_t* xp = xb + (ks*8 + (lane & 3)) * DSTR;
                uint32_t bf[4][2];
                #pragma unroll
                for (int nt = 0; nt < 4; nt++){
                    bf[nt][0] = xp[nt*8];
                    bf[nt][1] = xp[nt*8 + 4*DSTR];
                }
                #pragma unroll
                for (int mt = 0; mt < 4; mt++){
                    float4 a = w4[(ks>>1)*512 + (((ks&1)*8 + wm*4 + mt)*32 + lane)];
                    uint32_t a0=__float_as_uint(a.x), a1=__float_as_uint(a.y),
                             a2=__float_as_uint(a.z), a3=__float_as_uint(a.w);
                    #pragma unroll
                    for (int nt = 0; nt < 4; nt++)
                        mma_f16(acc[mt][nt], a0,a1,a2,a3, bf[nt][0], bf[nt][1]);
                }
            };

            // ks=0 first: get 16 HMMA queued on the tensor pipe...
            compute_ks(0);
            // ...then issue the kc+2 prefetch so the LDGSTS burst overlaps tensor
            // drain instead of sitting between compute-end and the next barrier.
            // (stage sl was last read at iteration kc-1, fenced by this kc's barrier)
            if (gl < totg) issue(gl, sl);
            asm volatile("cp.async.commit_group;");
            gl++;
            if (++sl == 3) sl = 0;
            compute_ks(1);
            compute_ks(2);
            compute_ks(3);
            if (++sc == 3) sc = 0;
        }

        #pragma unroll
        for (int mt = 0; mt < 4; mt++){
            int co = cb*128 + wm*64 + mt*16 + (lane >> 2);
            size_t rb = ((size_t)ub*512 + co)*1024;
            #pragma unroll
            for (int nt = 0; nt < 4; nt++){
                int tile = tile0 + wn*32 + nt*8 + (lane & 3)*2;
                __half2 v0 = __floats2half2_rn(acc[mt][nt][0], acc[mt][nt][1]);
                __half2 v1 = __floats2half2_rn(acc[mt][nt][2], acc[mt][nt][3]);
                *(__half2*)(g_m + rb + tile)          = v0;
                *(__half2*)(g_m + rb + 8*1024 + tile) = v1;
            }
        }
    }
}

// ---------------- inverse transform + fused demod: out = (A^T M A) * dscale ----------------
// grid (256, 16): 2 co per CTA; 128 threads per co, 8 tiles/thread via uint4 loads.
__global__ __launch_bounds__(256) void inv_kernel(float* __restrict__ out){
    __shared__ float red[256];
    int blk = blockIdx.x, b = blockIdx.y, tid = threadIdx.x;
    int half = tid >> 7;                   // co sub-index
    int lt   = tid & 127;
    int co = blk*2 + half;

    // fused demod: ds = CONV_SCALE / sqrt(CONV_SCALE^2 * sum_ci s^2*wsq + 1e-8)
    float partial = 0.f;
    #pragma unroll
    for (int k = 0; k < 4; k++){
        int ci = lt + k*128;
        float sv = g_s[b*512 + ci];
        partial = fmaf(sv*sv, g_wsq[co*512 + ci], partial);
    }
    red[tid] = partial;
    __syncthreads();
    #pragma unroll
    for (int off = 64; off > 0; off >>= 1){
        if (lt < off) red[tid] += red[tid + off];
        __syncthreads();
    }
    float ds = CONV_SCALE / sqrtf(CONV_SCALE*CONV_SCALE*red[half*128] + 1e-8f);

    // 8 tiles per thread: tiles 8p..8p+7 (one uint4 per u)
    int p = lt;
    const uint4* mp = (const uint4*)(g_m + ((size_t)(b*16)*512 + co)*1024);  // u-stride 65536 uint4
    uint4 raw[16];
    #pragma unroll
    for (int u = 0; u < 16; u++) raw[u] = mp[(size_t)u*65536 + p];

    float* op = out + ((size_t)(b*512 + co))*NPIX;
    int i = p >> 2, jb = (p & 3)*16;       // row pair i, col base 16*(p&3)

    #pragma unroll
    for (int sl = 0; sl < 4; sl++){
        float2 m[16];
        #pragma unroll
        for (int u = 0; u < 16; u++){
            uint32_t w = (sl==0) ? raw[u].x : (sl==1) ? raw[u].y : (sl==2) ? raw[u].z : raw[u].w;
            m[u] = __half22float2(*(__half2*)&w);
        }
        float2 p0[4], p1[4];
        #pragma unroll
        for (int c = 0; c < 4; c++){
            p0[c] = make_float2(m[c].x + m[4+c].x + m[8+c].x,
                                m[c].y + m[4+c].y + m[8+c].y);
            p1[c] = make_float2(m[4+c].x - m[8+c].x - m[12+c].x,
                                m[4+c].y - m[8+c].y - m[12+c].y);
        }
        float4 r0 = make_float4((p0[0].x+p0[1].x+p0[2].x)*ds, (p0[1].x-p0[2].x-p0[3].x)*ds,
                                (p0[0].y+p0[1].y+p0[2].y)*ds, (p0[1].y-p0[2].y-p0[3].y)*ds);
        float4 r1 = make_float4((p1[0].x+p1[1].x+p1[2].x)*ds, (p1[1].x-p1[2].x-p1[3].x)*ds,
                                (p1[0].y+p1[1].y+p1[2].y)*ds, (p1[1].y-p1[2].y-p1[3].y)*ds);
        *(float4*)(op + (2*i)*64   + jb + 4*sl) = r0;
        *(float4*)(op + (2*i+1)*64 + jb + 4*sl) = r1;
    }
}

// ---------------- launcher ----------------
extern "C" void kernel_launch(void* const* d_in, const int* in_sizes, int n_in,
                              void* d_out, int out_size){
    const float* input      = (const float*)d_in[0];
    const float* style      = (const float*)d_in[1];
    const float* weight     = (const float*)d_in[2];
    const float* mod_weight = (const float*)d_in[3];
    const float* mod_bias   = (const float*)d_in[4];
    float* out = (float*)d_out;

    cudaFuncSetAttribute(gemm_kernel, cudaFuncAttributeMaxDynamicSharedMemorySize, GEMM_SMEM);

    mod_kernel    <<<16, 512>>>(style, mod_weight, mod_bias);
    dtrans_kernel <<<dim3(256,20), 256>>>(input, weight);   // y<16: dtrans, y>=16: fused wtrans
    gemm_kernel   <<<GEMM_GRID, 256, GEMM_SMEM>>>();
    inv_kernel    <<<dim3(256,16), 256>>>(out);
}

// round 16
// speedup vs baseline: 3.1104x; 1.0081x over previous
#include <cuda_runtime.h>
#include <cuda_fp16.h>
#include <cstdint>
#include <cstddef>

#define BATCH 16
#define CIN   512
#define COUT  512
#define NPIX  4096
#define MOD_SCALE  0.044194173824159216f
#define CONV_SCALE 0.014731391274719739f

// Winograd F(2x2,3x3): 1024 tiles/image, 16 transform points (u)
// GEMM per (u,b): M_u[512co,1024t] = W_u[512co,512ci] * D_u[512ci,1024t]
// Persistent CTAs: 304 resident (2/SM), 128 threads, 4 warps of 64co x 64t,
// rolling 3-stage cp.async across tiles.

#define DSTR   136                          // 128 tiles + 8 pad words (8 mod 32 -> conflict-free)
#define DCH_B  (32*DSTR*4)                  // 17408 B per D stage (32 cipairs)
#define WCH_B  16384                        // 64ci x 128co fp16
#define STAGE_B (DCH_B + WCH_B)             // 33792 B
#define GEMM_SMEM (3*STAGE_B)               // 101376 B
#define GEMM_GRID 304

#define PSTR 72                             // dtrans smem plane stride (floats)

// ---------------- device scratch ----------------
__device__ float g_s[BATCH*CIN];
__device__ float g_wsq[COUT*CIN];
__device__ __align__(128) __half   g_wg[16*4*16*4096];                 // 8 MB transformed W, frag-packed
__device__ __align__(128) uint32_t g_d[(size_t)16*16*256*1024];        // 268 MB transformed input (f16x2 ci-pairs)
__device__ __align__(128) __half   g_m[(size_t)16*16*512*1024];        // 268 MB GEMM output M

// ---------------- mod: s[b][ci] = style @ (mod_weight*MOD_SCALE)^T + bias ----------------
__global__ __launch_bounds__(512) void mod_kernel(const float* __restrict__ style,
                                                  const float* __restrict__ mod_weight,
                                                  const float* __restrict__ mod_bias){
    __shared__ float st[512];
    int b = blockIdx.x, t = threadIdx.x;
    st[t] = style[b*512 + t];
    __syncthreads();
    const float* wr = mod_weight + t*512;
    float acc = 0.f;
    #pragma unroll 8
    for (int j = 0; j < 512; j++) acc = fmaf(st[j], wr[j], acc);
    g_s[b*512 + t] = acc * MOD_SCALE + mod_bias[t];
}

// ---------------- dtrans (grid y<16) + fused wtrans (grid y>=16) ----------------
__global__ __launch_bounds__(256) void dtrans_kernel(const float* __restrict__ x,
                                                     const float* __restrict__ w){
    __shared__ float sp[2*66*PSTR];        // two padded planes, 38016 B
    int tid = threadIdx.x;

    if (blockIdx.y >= 16){
        // ---- wtrans: U = G g G^T (frag-packed fp16) + fused wsq ----
        int blk = (blockIdx.y - 16)*256 + blockIdx.x;   // 0..1023
        int i = blk*256 + tid;                          // 262144 = co*512+ci
        int co = i >> 9, ci = i & 511;
        const float* p = w + (size_t)i*9;
        float g[3][3];
        float sq = 0.f;
        #pragma unroll
        for (int r = 0; r < 3; r++)
            #pragma unroll
            for (int c = 0; c < 3; c++){ g[r][c] = p[r*3+c]; sq = fmaf(g[r][c], g[r][c], sq); }
        g_wsq[i] = sq;
        float t[4][3];
        #pragma unroll
        for (int c = 0; c < 3; c++){
            t[0][c] = g[0][c];
            t[1][c] = 0.5f*(g[0][c]+g[1][c]+g[2][c]);
            t[2][c] = 0.5f*(g[0][c]-g[1][c]+g[2][c]);
            t[3][c] = g[2][c];
        }
        float U[16];
        #pragma unroll
        for (int r = 0; r < 4; r++){
            U[r*4+0] = t[r][0];
            U[r*4+1] = 0.5f*(t[r][0]+t[r][1]+t[r][2]);
            U[r*4+2] = 0.5f*(t[r][0]-t[r][1]+t[r][2]);
            U[r*4+3] = t[r][2];
        }
        int kc = ci>>5, c5 = ci&31, ks = c5>>4, cc = c5&15;
        int lane = (co&7)*4 + ((cc>>1)&3);
        int r    = ((co>>3)&1) + ((cc>>3)&1)*2;
        int mt   = (co>>4)&7, cb = co>>7;
        size_t boff = ((size_t)(cb*16 + kc))*4096 + (size_t)(((ks*8+mt)*32+lane)<<3) + r*2 + (cc&1);
        #pragma unroll
        for (int u = 0; u < 16; u++)
            g_wg[boff + (size_t)u*262144] = __float2half_rn(U[u]);
        return;
    }

    // ---- dtrans: D = B^T x B * s ----
    int cp = blockIdx.x, b = blockIdx.y;
    const float* x0 = x + ((size_t)(b*512 + cp*2))*NPIX;
    const float* x1 = x0 + NPIX;
    float s0 = g_s[b*512 + cp*2];
    float s1 = g_s[b*512 + cp*2 + 1];

    float4 z = make_float4(0.f,0.f,0.f,0.f);
    for (int i = tid; i < 2*66*PSTR/4; i += 256) ((float4*)sp)[i] = z;
    __syncthreads();

    unsigned spu = (unsigned)__cvta_generic_to_shared(sp);
    #pragma unroll
    for (int k = 0; k < 8; k++){
        int t = tid + k*256;               // 0..2047
        int p  = t >> 10;
        int rm = t & 1023;
        int ir = rm >> 4, ch = rm & 15;
        unsigned dst = spu + (unsigned)((p*66*PSTR + (ir+1)*PSTR + 4 + ch*4)*4);
        const float* src = (p ? x1 : x0) + ir*64 + ch*4;
        asm volatile("cp.async.cg.shared.global [%0], [%1], 16;" :: "r"(dst), "l"(src));
    }
    asm volatile("cp.async.commit_group;");
    asm volatile("cp.async.wait_group 0;");
    __syncthreads();

    const float* sp0 = sp;
    const float* sp1 = sp + 66*PSTR;

    auto tilepack = [&](int i, int j, uint32_t* outp){
        float dx[4][4], dy[4][4];
        int base = (2*i)*PSTR + 2*j + 3;
        #pragma unroll
        for (int rr = 0; rr < 4; rr++)
            #pragma unroll
            for (int cc = 0; cc < 4; cc++){
                dx[rr][cc] = sp0[base + rr*PSTR + cc] * s0;
                dy[rr][cc] = sp1[base + rr*PSTR + cc] * s1;
            }
        float tx[4][4], ty[4][4];
        #pragma unroll
        for (int c = 0; c < 4; c++){
            tx[0][c] = dx[0][c] - dx[2][c];  ty[0][c] = dy[0][c] - dy[2][c];
            tx[1][c] = dx[1][c] + dx[2][c];  ty[1][c] = dy[1][c] + dy[2][c];
            tx[2][c] = dx[2][c] - dx[1][c];  ty[2][c] = dy[2][c] - dy[1][c];
            tx[3][c] = dx[1][c] - dx[3][c];  ty[3][c] = dy[1][c] - dy[3][c];
        }
        #pragma unroll
        for (int r = 0; r < 4; r++){
            __half2 h0 = __floats2half2_rn(tx[r][0] - tx[r][2], ty[r][0] - ty[r][2]);
            __half2 h1 = __floats2half2_rn(tx[r][1] + tx[r][2], ty[r][1] + ty[r][2]);
            __half2 h2 = __floats2half2_rn(tx[r][2] - tx[r][1], ty[r][2] - ty[r][1]);
            __half2 h3 = __floats2half2_rn(tx[r][1] - tx[r][3], ty[r][1] - ty[r][3]);
            outp[r*4+0] = *(uint32_t*)&h0;
            outp[r*4+1] = *(uint32_t*)&h1;
            outp[r*4+2] = *(uint32_t*)&h2;
            outp[r*4+3] = *(uint32_t*)&h3;
        }
    };

    #pragma unroll
    for (int pp = 0; pp < 2; pp++){
        int q = pp*256 + tid;              // tile-pair index: tiles 2q, 2q+1
        int i = q >> 4, j0 = (q & 15)*2;
        uint32_t ua[16], ub[16];
        tilepack(i, j0,   ua);
        tilepack(i, j0+1, ub);
        size_t gbase = ((size_t)(b*16)*256 + cp)*1024 + 2*q;
        #pragma unroll
        for (int u = 0; u < 16; u++)
            *(uint2*)&g_d[gbase + (size_t)u*262144] = make_uint2(ua[u], ub[u]);
    }
}

// ---------------- GEMM: fp16 m16n8k16, fp32 accum, persistent CTAs, rolling 3-stage ----------------
// 4 warps of 64co x 64t (halves redundant W-fragment smem reads vs 8x 64x32 warps)
__device__ __forceinline__ void mma_f16(float* c, uint32_t a0,uint32_t a1,uint32_t a2,uint32_t a3,
                                        uint32_t b0,uint32_t b1){
    asm volatile("mma.sync.aligned.m16n8k16.row.col.f32.f16.f16.f32 "
        "{%0,%1,%2,%3}, {%4,%5,%6,%7}, {%8,%9}, {%0,%1,%2,%3};"
        : "+f"(c[0]), "+f"(c[1]), "+f"(c[2]), "+f"(c[3])
        : "r"(a0), "r"(a1), "r"(a2), "r"(a3), "r"(b0), "r"(b1));
}

__global__ __launch_bounds__(128,2) void gemm_kernel(){
    extern __shared__ char smem[];
    const int tid  = threadIdx.x;
    const int lane = tid & 31;
    const int warp = tid >> 5;        // 0..3
    const int wm   = warp >> 1;       // co half (64)
    const int wn   = warp & 1;        // tile half (64)
    const int bx   = blockIdx.x;

    unsigned sm_u = (unsigned)__cvta_generic_to_shared(smem);

    const int njobs = (8192 - bx + GEMM_GRID - 1) / GEMM_GRID;
    const int totg  = njobs * 8;

    auto issue = [&](int g, int s){
        int jw = g >> 3, kc = g & 7;
        int wk = bx + jw * GEMM_GRID;
        int x = wk & 31, ub = wk >> 5;
        int cb = x >> 3, nb = x & 7;
        const uint4* dsrc = (const uint4*)g_d + (size_t)ub*65536 + (size_t)(nb*32);
        const uint4* wsrc = (const uint4*)g_wg + (size_t)(ub & 15)*32768 + (size_t)cb*8192;
        unsigned base = sm_u + (unsigned)(s * STAGE_B);
        #pragma unroll
        for (int k = 0; k < 8; k++){
            int idx = tid + k*128;        // 0..1023
            int cp = idx >> 5, q = idx & 31;
            asm volatile("cp.async.cg.shared.global [%0], [%1], 16;"
                         :: "r"(base + (unsigned)((cp*DSTR + q*4)*4)),
                            "l"(dsrc + (size_t)(kc*32 + cp)*256 + q));
        }
        #pragma unroll
        for (int k = 0; k < 8; k++){
            int idx = tid + k*128;        // 0..1023
            asm volatile("cp.async.cg.shared.global [%0], [%1], 16;"
                         :: "r"(base + (unsigned)(DCH_B + idx*16)), "l"(wsrc + kc*1024 + idx));
        }
    };

    issue(0, 0);
    asm volatile("cp.async.commit_group;");
    issue(1, 1);
    asm volatile("cp.async.commit_group;");
    int gl = 2, sl = 2;
    int sc = 0;

    for (int jw = 0; jw < njobs; jw++){
        int wk = bx + jw * GEMM_GRID;
        int x = wk & 31, ub = wk >> 5;
        int cb = x >> 3, nb = x & 7;
        int tile0 = nb * 128;

        float acc[4][8][4];
        #pragma unroll
        for (int i=0;i<4;i++)
          #pragma unroll
          for (int j=0;j<8;j++)
            #pragma unroll
            for (int k=0;k<4;k++) acc[i][j][k]=0.f;

        for (int kc = 0; kc < 8; kc++){
            asm volatile("cp.async.wait_group 1;");
            __syncthreads();

            const uint32_t* xb = (const uint32_t*)(smem + sc*STAGE_B) + wn*64 + (lane >> 2);
            const float4*  w4 = (const float4*)(smem + sc*STAGE_B + DCH_B);

            auto compute_ks = [&](int ks){
                const uint32_t* xp = xb + (ks*8 + (lane & 3)) * DSTR;
                uint32_t bf[8][2];
                #pragma unroll
                for (int nt = 0; nt < 8; nt++){
                    bf[nt][0] = xp[nt*8];
                    bf[nt][1] = xp[nt*8 + 4*DSTR];
                }
                #pragma unroll
                for (int mt = 0; mt < 4; mt++){
                    float4 a = w4[(ks>>1)*512 + (((ks&1)*8 + wm*4 + mt)*32 + lane)];
                    uint32_t a0=__float_as_uint(a.x), a1=__float_as_uint(a.y),
                             a2=__float_as_uint(a.z), a3=__float_as_uint(a.w);
                    #pragma unroll
                    for (int nt = 0; nt < 8; nt++)
                        mma_f16(acc[mt][nt], a0,a1,a2,a3, bf[nt][0], bf[nt][1]);
                }
            };

            compute_ks(0);
            // prefetch kc+2 overlapped with tensor drain
            if (gl < totg) issue(gl, sl);
            asm volatile("cp.async.commit_group;");
            gl++;
            if (++sl == 3) sl = 0;
            compute_ks(1);
            compute_ks(2);
            compute_ks(3);
            if (++sc == 3) sc = 0;
        }

        #pragma unroll
        for (int mt = 0; mt < 4; mt++){
            int co = cb*128 + wm*64 + mt*16 + (lane >> 2);
            size_t rb = ((size_t)ub*512 + co)*1024;
            #pragma unroll
            for (int nt = 0; nt < 8; nt++){
                int tile = tile0 + wn*64 + nt*8 + (lane & 3)*2;
                __half2 v0 = __floats2half2_rn(acc[mt][nt][0], acc[mt][nt][1]);
                __half2 v1 = __floats2half2_rn(acc[mt][nt][2], acc[mt][nt][3]);
                *(__half2*)(g_m + rb + tile)          = v0;
                *(__half2*)(g_m + rb + 8*1024 + tile) = v1;
            }
        }
    }
}

// ---------------- inverse transform + fused demod: out = (A^T M A) * dscale ----------------
__global__ __launch_bounds__(256) void inv_kernel(float* __restrict__ out){
    __shared__ float red[256];
    int blk = blockIdx.x, b = blockIdx.y, tid = threadIdx.x;
    int half = tid >> 7;
    int lt   = tid & 127;
    int co = blk*2 + half;

    float partial = 0.f;
    #pragma unroll
    for (int k = 0; k < 4; k++){
        int ci = lt + k*128;
        float sv = g_s[b*512 + ci];
        partial = fmaf(sv*sv, g_wsq[co*512 + ci], partial);
    }
    red[tid] = partial;
    __syncthreads();
    #pragma unroll
    for (int off = 64; off > 0; off >>= 1){
        if (lt < off) red[tid] += red[tid + off];
        __syncthreads();
    }
    float ds = CONV_SCALE / sqrtf(CONV_SCALE*CONV_SCALE*red[half*128] + 1e-8f);

    int p = lt;
    const uint4* mp = (const uint4*)(g_m + ((size_t)(b*16)*512 + co)*1024);
    uint4 raw[16];
    #pragma unroll
    for (int u = 0; u < 16; u++) raw[u] = mp[(size_t)u*65536 + p];

    float* op = out + ((size_t)(b*512 + co))*NPIX;
    int i = p >> 2, jb = (p & 3)*16;

    #pragma unroll
    for (int sl = 0; sl < 4; sl++){
        float2 m[16];
        #pragma unroll
        for (int u = 0; u < 16; u++){
            uint32_t w = (sl==0) ? raw[u].x : (sl==1) ? raw[u].y : (sl==2) ? raw[u].z : raw[u].w;
            m[u] = __half22float2(*(__half2*)&w);
        }
        float2 p0[4], p1[4];
        #pragma unroll
        for (int c = 0; c < 4; c++){
            p0[c] = make_float2(m[c].x + m[4+c].x + m[8+c].x,
                                m[c].y + m[4+c].y + m[8+c].y);
            p1[c] = make_float2(m[4+c].x - m[8+c].x - m[12+c].x,
                                m[4+c].y - m[8+c].y - m[12+c].y);
        }
        float4 r0 = make_float4((p0[0].x+p0[1].x+p0[2].x)*ds, (p0[1].x-p0[2].x-p0[3].x)*ds,
                                (p0[0].y+p0[1].y+p0[2].y)*ds, (p0[1].y-p0[2].y-p0[3].y)*ds);
        float4 r1 = make_float4((p1[0].x+p1[1].x+p1[2].x)*ds, (p1[1].x-p1[2].x-p1[3].x)*ds,
                                (p1[0].y+p1[1].y+p1[2].y)*ds, (p1[1].y-p1[2].y-p1[3].y)*ds);
        *(float4*)(op + (2*i)*64   + jb + 4*sl) = r0;
        *(float4*)(op + (2*i+1)*64 + jb + 4*sl) = r1;
    }
}

// ---------------- launcher ----------------
extern "C" void kernel_launch(void* const* d_in, const int* in_sizes, int n_in,
                              void* d_out, int out_size){
    const float* input      = (const float*)d_in[0];
    const float* style      = (const float*)d_in[1];
    const float* weight     = (const float*)d_in[2];
    const float* mod_weight = (const float*)d_in[3];
    const float* mod_bias   = (const float*)d_in[4];
    float* out = (float*)d_out;

    cudaFuncSetAttribute(gemm_kernel, cudaFuncAttributeMaxDynamicSharedMemorySize, GEMM_SMEM);

    mod_kernel    <<<16, 512>>>(style, mod_weight, mod_bias);
    dtrans_kernel <<<dim3(256,20), 256>>>(input, weight);   // y<16: dtrans, y>=16: fused wtrans
    gemm_kernel   <<<GEMM_GRID, 128, GEMM_SMEM>>>();
    inv_kernel    <<<dim3(256,16), 256>>>(out);
}